// round 3
// baseline (speedup 1.0000x reference)
#include <cuda_runtime.h>
#include <math.h>

// Problem constants
#define CD  1024      // model dim
#define CH  16        // heads
#define CF  4096      // ffn dim
#define CE  8         // experts
#define CK  2         // top-k
#define CB  2         // batch
#define CS  2048      // seq
#define CN  (CB*CS)   // 4096 tokens
#define CDH 64        // head dim
#define CNK (CN*CK)   // 8192 assignments

// ---------------- scratch (static device globals; no allocation) ----------------
__device__ float g_q[CN*CD];
__device__ float g_k[CN*CD];
__device__ float g_v[CN*CD];
__device__ float g_attn[CN*CD];
__device__ float g_tmp[CN*CD];
__device__ float g_x1[CN*CD];
__device__ float g_x2[CN*CD];
__device__ float g_h[(size_t)CNK*CF];      // 128 MB expert hidden
__device__ float g_yslot[(size_t)CNK*CD];  // 32 MB per-slot expert outputs
__device__ float g_gate[CNK];
__device__ int   g_eid[CNK];
__device__ int   g_cnt[CE];
__device__ int   g_off[CE];
__device__ int   g_cur[CE];
__device__ int   g_list[CNK];
__device__ float g_auxp[32][16];

// ---------------- core SGEMM tile body 128x128x8, 256 threads, 8x8 micro ----------------
// Double-buffered smem pipeline: LDG(t+1) -> compute(t) -> STS(t+1) -> one BAR.
// MODE 0: C[M,N] = A[M,K] @ B[K,N] + bias              (dense)
// MODE 1: expert fc1: gather rows of A via g_list, C packed rows (g_off[e]+r), +bias, relu
// MODE 2: expert fc2: A packed rows, C scattered to row g_list[...], (acc+bias)*gate
template<int MODE>
__device__ __forceinline__ void sgemm_body(const float* __restrict__ A,
                                           const float* __restrict__ Bw,
                                           const float* __restrict__ bias,
                                           float* __restrict__ C,
                                           int Meff, int base, int N, int K,
                                           int bm, int bn)
{
    __shared__ float As[2][8][128];
    __shared__ float Bs[2][8][128];

    int tid  = threadIdx.x;
    int arow = tid >> 1;            // 0..127
    int ak   = (tid & 1) << 2;      // 0 or 4
    int brow = tid >> 5;            // 0..7
    int bcol = (tid & 31) << 2;     // 0..124

    int r_ld = bm + arow;
    bool avalid = r_ld < Meff;
    const float* Arow;
    if (MODE == 1) {
        int a = avalid ? g_list[base + r_ld] : 0;
        Arow = A + (size_t)(a >> 1) * K;
    } else if (MODE == 2) {
        int rr = avalid ? (base + r_ld) : base;
        Arow = A + (size_t)rr * K;
    } else {
        Arow = A + (size_t)(avalid ? r_ld : 0) * K;
    }
    const float* Bp = Bw + (size_t)brow * N + bn + bcol;

    float acc[8][8];
#pragma unroll
    for (int i = 0; i < 8; i++)
#pragma unroll
        for (int j = 0; j < 8; j++) acc[i][j] = 0.f;

    int ty = tid >> 4, tx = tid & 15;
    int nT = K >> 3;

    { // preload tile 0
        float4 av = avalid ? *(const float4*)(Arow + ak) : make_float4(0.f,0.f,0.f,0.f);
        float4 bv = *(const float4*)(Bp);
        As[0][ak+0][arow] = av.x; As[0][ak+1][arow] = av.y;
        As[0][ak+2][arow] = av.z; As[0][ak+3][arow] = av.w;
        *(float4*)(&Bs[0][brow][bcol]) = bv;
    }
    __syncthreads();

    for (int t = 0; t < nT; t++) {
        int cur = t & 1;
        bool pf = (t + 1) < nT;
        float4 av, bv;
        if (pf) {   // issue global loads early; consumed only after compute
            av = avalid ? *(const float4*)(Arow + (t+1)*8 + ak) : make_float4(0.f,0.f,0.f,0.f);
            bv = *(const float4*)(Bp + (size_t)(t+1) * 8 * N);
        }
#pragma unroll
        for (int kk = 0; kk < 8; kk++) {
            float4 a0 = *(const float4*)(&As[cur][kk][ty*8]);
            float4 a1 = *(const float4*)(&As[cur][kk][ty*8+4]);
            float4 b0 = *(const float4*)(&Bs[cur][kk][tx*8]);
            float4 b1 = *(const float4*)(&Bs[cur][kk][tx*8+4]);
            float ar[8] = {a0.x,a0.y,a0.z,a0.w,a1.x,a1.y,a1.z,a1.w};
            float br[8] = {b0.x,b0.y,b0.z,b0.w,b1.x,b1.y,b1.z,b1.w};
#pragma unroll
            for (int i = 0; i < 8; i++)
#pragma unroll
                for (int j = 0; j < 8; j++) acc[i][j] += ar[i]*br[j];
        }
        if (pf) {
            int nx = cur ^ 1;
            As[nx][ak+0][arow] = av.x; As[nx][ak+1][arow] = av.y;
            As[nx][ak+2][arow] = av.z; As[nx][ak+3][arow] = av.w;
            *(float4*)(&Bs[nx][brow][bcol]) = bv;
        }
        __syncthreads();
    }

#pragma unroll
    for (int i = 0; i < 8; i++) {
        int r = bm + ty*8 + i;
        if (r >= Meff) continue;
        float* Crow;
        float scale = 1.f;
        if (MODE == 2) {
            int a  = g_list[base + r];
            scale  = g_gate[a];
            Crow   = C + (size_t)a * N;
        } else if (MODE == 1) {
            Crow   = C + (size_t)(base + r) * N;
        } else {
            Crow   = C + (size_t)r * N;
        }
#pragma unroll
        for (int j = 0; j < 8; j++) {
            int c = bn + tx*8 + j;
            float vv = acc[i][j] + bias[c];
            if (MODE == 1) vv = fmaxf(vv, 0.f);
            if (MODE == 2) vv *= scale;
            Crow[c] = vv;
        }
    }
}

// dense single GEMM
__global__ void __launch_bounds__(256) sgemm_k(const float* __restrict__ A,
                                               const float* __restrict__ Bw,
                                               const float* __restrict__ bias,
                                               float* __restrict__ C,
                                               int M, int N, int K)
{
    sgemm_body<0>(A, Bw, bias, C, M, 0, N, K, blockIdx.y * 128, blockIdx.x * 128);
}

// fused QKV projection: blockIdx.z selects (A, W, bias, C) triple.
// Self-attn: Aq=Ak=Av=x. Cross-attn: Aq=x1, Ak=Av=enc.
__global__ void __launch_bounds__(256) qkv_gemm_k(const float* __restrict__ Aq,
                                                  const float* __restrict__ Akv,
                                                  const float* __restrict__ Wq,
                                                  const float* __restrict__ Wk,
                                                  const float* __restrict__ Wv,
                                                  const float* __restrict__ bq,
                                                  const float* __restrict__ bk,
                                                  const float* __restrict__ bv,
                                                  float* __restrict__ Cq,
                                                  float* __restrict__ Ck,
                                                  float* __restrict__ Cv)
{
    int z = blockIdx.z;
    const float* A  = (z == 0) ? Aq : Akv;
    const float* W  = (z == 0) ? Wq : (z == 1) ? Wk : Wv;
    const float* bb = (z == 0) ? bq : (z == 1) ? bk : bv;
    float*       C  = (z == 0) ? Cq : (z == 1) ? Ck : Cv;
    sgemm_body<0>(A, W, bb, C, CN, 0, CD, CD, blockIdx.y * 128, blockIdx.x * 128);
}

// grouped expert GEMMs (MODE 1 = fc1+relu gather, MODE 2 = fc2 scatter*gate)
template<int MODE>
__global__ void __launch_bounds__(256) moe_gemm_k(const float* __restrict__ A,
                                                  const float* __restrict__ Bw,
                                                  const float* __restrict__ bias,
                                                  float* __restrict__ C,
                                                  int N, int K)
{
    int e = blockIdx.z;
    int Meff = g_cnt[e];
    int base = g_off[e];
    int bm = blockIdx.y * 128;
    if (bm >= Meff) return;
    sgemm_body<MODE>(A, Bw + (size_t)e * K * N, bias + (size_t)e * N, C,
                     Meff, base, N, K, bm, blockIdx.x * 128);
}

// ---------------- flash attention fp32; 64 q-rows x 64 kv per tile ----------------
#define ATTN_SMEM (4*64*68*4)

__global__ void __launch_bounds__(256) attn_k(const float* __restrict__ Q,
                                              const float* __restrict__ Kg,
                                              const float* __restrict__ Vg,
                                              float* __restrict__ O)
{
    extern __shared__ float sm[];
    float* qs = sm;
    float* ks = sm + 64*68;
    float* vs = sm + 2*64*68;
    float* ps = sm + 3*64*68;

    int tid = threadIdx.x;
    int h = blockIdx.y, b = blockIdx.z;
    int q0 = blockIdx.x * 64;
    size_t basebh = ((size_t)b*CS)*CD + (size_t)h*CDH;

    int lrow = tid >> 2;          // 0..63
    int lseg = (tid & 3) << 4;    // 0,16,32,48

    { // load Q tile once
        const float4* src = (const float4*)(Q + basebh + (size_t)(q0+lrow)*CD + lseg);
        float4* dst = (float4*)(qs + lrow*68 + lseg);
#pragma unroll
        for (int i = 0; i < 4; i++) dst[i] = src[i];
    }

    int row = lrow;
    int c0  = lseg;
    float o[16];
#pragma unroll
    for (int i = 0; i < 16; i++) o[i] = 0.f;
    float m = -1e30f, l = 0.f;

    for (int kv0 = 0; kv0 < CS; kv0 += 64) {
        __syncthreads();   // prev PV done (and Q store visible)
        {
            const float4* ksrc = (const float4*)(Kg + basebh + (size_t)(kv0+lrow)*CD + lseg);
            const float4* vsrc = (const float4*)(Vg + basebh + (size_t)(kv0+lrow)*CD + lseg);
            float4* kd = (float4*)(ks + lrow*68 + lseg);
            float4* vd = (float4*)(vs + lrow*68 + lseg);
#pragma unroll
            for (int i = 0; i < 4; i++) { kd[i] = ksrc[i]; vd[i] = vsrc[i]; }
        }
        __syncthreads();

        float s[16];
#pragma unroll
        for (int j = 0; j < 16; j++) s[j] = 0.f;
#pragma unroll 4
        for (int d4 = 0; d4 < 16; d4++) {
            float4 qv = *(const float4*)(qs + row*68 + d4*4);
#pragma unroll
            for (int j = 0; j < 16; j++) {
                float4 kv = *(const float4*)(ks + (c0+j)*68 + d4*4);
                s[j] += qv.x*kv.x + qv.y*kv.y + qv.z*kv.z + qv.w*kv.w;
            }
        }
        float mx = -1e30f;
#pragma unroll
        for (int j = 0; j < 16; j++) { s[j] *= 0.125f; mx = fmaxf(mx, s[j]); }
        mx = fmaxf(mx, __shfl_xor_sync(0xffffffffu, mx, 1));
        mx = fmaxf(mx, __shfl_xor_sync(0xffffffffu, mx, 2));
        float mnew = fmaxf(m, mx);
        float corr = __expf(m - mnew);
        float ls = 0.f;
#pragma unroll
        for (int j = 0; j < 16; j++) { s[j] = __expf(s[j] - mnew); ls += s[j]; }
        ls += __shfl_xor_sync(0xffffffffu, ls, 1);
        ls += __shfl_xor_sync(0xffffffffu, ls, 2);
        l = l*corr + ls;
        m = mnew;
#pragma unroll
        for (int i = 0; i < 16; i++) o[i] *= corr;
#pragma unroll
        for (int j = 0; j < 16; j += 4)
            *(float4*)(ps + row*68 + c0 + j) = make_float4(s[j], s[j+1], s[j+2], s[j+3]);
        __syncthreads();
#pragma unroll 8
        for (int c = 0; c < 64; c++) {
            float p = ps[row*68 + c];
            const float4* vv = (const float4*)(vs + c*68 + c0);
            float4 v0 = vv[0], v1 = vv[1], v2 = vv[2], v3 = vv[3];
            o[0]  += p*v0.x; o[1]  += p*v0.y; o[2]  += p*v0.z; o[3]  += p*v0.w;
            o[4]  += p*v1.x; o[5]  += p*v1.y; o[6]  += p*v1.z; o[7]  += p*v1.w;
            o[8]  += p*v2.x; o[9]  += p*v2.y; o[10] += p*v2.z; o[11] += p*v2.w;
            o[12] += p*v3.x; o[13] += p*v3.y; o[14] += p*v3.z; o[15] += p*v3.w;
        }
    }
    float inv = 1.f / l;
    float* op = O + basebh + (size_t)(q0+row)*CD + c0;
#pragma unroll
    for (int j = 0; j < 16; j += 4)
        *(float4*)(op + j) = make_float4(o[j]*inv, o[j+1]*inv, o[j+2]*inv, o[j+3]*inv);
}

// ---------------- block reduce helper ----------------
__device__ __forceinline__ float blk_sum(float v, float* red)
{
    int lane = threadIdx.x & 31, w = threadIdx.x >> 5;
#pragma unroll
    for (int o = 16; o; o >>= 1) v += __shfl_xor_sync(0xffffffffu, v, o);
    if (lane == 0) red[w] = v;
    __syncthreads();
    if (threadIdx.x == 0) {
        float t = 0.f;
        for (int i = 0; i < 8; i++) t += red[i];
        red[8] = t;
    }
    __syncthreads();
    float r = red[8];
    __syncthreads();
    return r;
}

// ---------------- residual add + layernorm (row = 1024) ----------------
__global__ void __launch_bounds__(256) add_ln_k(const float* __restrict__ a,
                                                const float* __restrict__ b,
                                                const float* __restrict__ gg,
                                                const float* __restrict__ bb,
                                                float* __restrict__ out)
{
    __shared__ float red[9];
    size_t base = (size_t)blockIdx.x * CD;
    int tid = threadIdx.x;
    float v[4];
    float s = 0.f;
#pragma unroll
    for (int i = 0; i < 4; i++) { int c = tid + (i<<8); float t = a[base+c] + b[base+c]; v[i] = t; s += t; }
    float mean = blk_sum(s, red) * (1.f/CD);
    float qq = 0.f;
#pragma unroll
    for (int i = 0; i < 4; i++) { float d = v[i]-mean; qq += d*d; }
    float var = blk_sum(qq, red) * (1.f/CD);
    float rstd = rsqrtf(var + 1e-5f);
#pragma unroll
    for (int i = 0; i < 4; i++) { int c = tid + (i<<8); out[base+c] = (v[i]-mean)*rstd*gg[c] + bb[c]; }
}

// combine the 2 expert slots + residual + LN3, write final x into d_out
__global__ void __launch_bounds__(256) moe_ln_k(const float* __restrict__ a,
                                                const float* __restrict__ gg,
                                                const float* __restrict__ bb,
                                                float* __restrict__ out)
{
    __shared__ float red[9];
    int rowid = blockIdx.x;
    size_t base = (size_t)rowid * CD;
    const float* y0 = g_yslot + (size_t)(2*rowid) * CD;
    const float* y1 = y0 + CD;
    int tid = threadIdx.x;
    float v[4];
    float s = 0.f;
#pragma unroll
    for (int i = 0; i < 4; i++) { int c = tid + (i<<8); float t = a[base+c] + y0[c] + y1[c]; v[i] = t; s += t; }
    float mean = blk_sum(s, red) * (1.f/CD);
    float qq = 0.f;
#pragma unroll
    for (int i = 0; i < 4; i++) { float d = v[i]-mean; qq += d*d; }
    float var = blk_sum(qq, red) * (1.f/CD);
    float rstd = rsqrtf(var + 1e-5f);
#pragma unroll
    for (int i = 0; i < 4; i++) { int c = tid + (i<<8); out[base+c] = (v[i]-mean)*rstd*gg[c] + bb[c]; }
}

// ---------------- router: softmax over 8 logits, top-2, renormalized gates ----------------
__global__ void __launch_bounds__(256) router_k(const float* __restrict__ x,
                                                const float* __restrict__ rw,
                                                const float* __restrict__ rb)
{
    int gw = (blockIdx.x * blockDim.x + threadIdx.x) >> 5;
    int lane = threadIdx.x & 31;
    if (gw >= CN) return;
    const float* xr = x + (size_t)gw * CD;
    float acc[8];
#pragma unroll
    for (int e = 0; e < 8; e++) acc[e] = 0.f;
    for (int d = lane; d < CD; d += 32) {
        float xv = xr[d];
        const float4* wp = (const float4*)(rw + d*CE);
        float4 w0 = wp[0], w1 = wp[1];
        acc[0] += xv*w0.x; acc[1] += xv*w0.y; acc[2] += xv*w0.z; acc[3] += xv*w0.w;
        acc[4] += xv*w1.x; acc[5] += xv*w1.y; acc[6] += xv*w1.z; acc[7] += xv*w1.w;
    }
#pragma unroll
    for (int e = 0; e < 8; e++)
#pragma unroll
        for (int o = 16; o; o >>= 1) acc[e] += __shfl_xor_sync(0xffffffffu, acc[e], o);
    if (lane == 0) {
        float p[8];
        float mx = -1e30f;
#pragma unroll
        for (int e = 0; e < 8; e++) { p[e] = acc[e] + rb[e]; mx = fmaxf(mx, p[e]); }
        float se = 0.f;
#pragma unroll
        for (int e = 0; e < 8; e++) { p[e] = __expf(p[e]-mx); se += p[e]; }
        float inv = 1.f/se;
#pragma unroll
        for (int e = 0; e < 8; e++) p[e] *= inv;
        int i1 = 0;
#pragma unroll
        for (int e = 1; e < 8; e++) if (p[e] > p[i1]) i1 = e;
        int i2 = -1;
#pragma unroll
        for (int e = 0; e < 8; e++) if (e != i1 && (i2 < 0 || p[e] > p[i2])) i2 = e;
        float s2 = p[i1] + p[i2];
        g_eid[2*gw]   = i1;  g_eid[2*gw+1]   = i2;
        g_gate[2*gw]  = p[i1]/s2; g_gate[2*gw+1] = p[i2]/s2;
    }
}

// ---------------- MoE dispatch bookkeeping ----------------
__global__ void moe_zero_k() { if (threadIdx.x < CE) g_cnt[threadIdx.x] = 0; }
__global__ void moe_count_k() {
    int i = blockIdx.x * blockDim.x + threadIdx.x;
    if (i < CNK) atomicAdd(&g_cnt[g_eid[i]], 1);
}
__global__ void moe_off_k() {
    if (threadIdx.x == 0) {
        int s = 0;
        for (int e = 0; e < CE; e++) { g_off[e] = s; g_cur[e] = s; s += g_cnt[e]; }
    }
}
__global__ void moe_build_k() {
    int i = blockIdx.x * blockDim.x + threadIdx.x;
    if (i < CNK) {
        int pos = atomicAdd(&g_cur[g_eid[i]], 1);
        g_list[pos] = i;
    }
}

// ---------------- aux loss: two-stage deterministic reduction ----------------
__global__ void __launch_bounds__(256) aux_partial_k(const float* __restrict__ x,
                                                     const float* __restrict__ rw,
                                                     const float* __restrict__ rb)
{
    __shared__ float simp[8][8];
    __shared__ float scnt[8][8];
    int tid = threadIdx.x, lane = tid & 31, w = tid >> 5;
    float imp[8], cnt[8];
#pragma unroll
    for (int e = 0; e < 8; e++) { imp[e] = 0.f; cnt[e] = 0.f; }
    for (int i = 0; i < 16; i++) {
        int t = blockIdx.x * 128 + w * 16 + i;
        const float* xr = x + (size_t)t * CD;
        float acc[8];
#pragma unroll
        for (int e = 0; e < 8; e++) acc[e] = 0.f;
        for (int d = lane; d < CD; d += 32) {
            float xv = xr[d];
            const float4* wp = (const float4*)(rw + d*CE);
            float4 w0 = wp[0], w1 = wp[1];
            acc[0] += xv*w0.x; acc[1] += xv*w0.y; acc[2] += xv*w0.z; acc[3] += xv*w0.w;
            acc[4] += xv*w1.x; acc[5] += xv*w1.y; acc[6] += xv*w1.z; acc[7] += xv*w1.w;
        }
#pragma unroll
        for (int e = 0; e < 8; e++)
#pragma unroll
            for (int o = 16; o; o >>= 1) acc[e] += __shfl_xor_sync(0xffffffffu, acc[e], o);
        if (lane == 0) {
            float p[8];
            float mx = -1e30f;
#pragma unroll
            for (int e = 0; e < 8; e++) { p[e] = acc[e] + rb[e]; mx = fmaxf(mx, p[e]); }
            float se = 0.f;
#pragma unroll
            for (int e = 0; e < 8; e++) { p[e] = __expf(p[e]-mx); se += p[e]; }
            float inv = 1.f/se;
#pragma unroll
            for (int e = 0; e < 8; e++) { p[e] *= inv; imp[e] += p[e]; }
            int i1 = 0;
#pragma unroll
            for (int e = 1; e < 8; e++) if (p[e] > p[i1]) i1 = e;
            int i2 = -1;
#pragma unroll
            for (int e = 0; e < 8; e++) if (e != i1 && (i2 < 0 || p[e] > p[i2])) i2 = e;
            cnt[i1] += 1.f; cnt[i2] += 1.f;
        }
    }
    if (lane == 0) {
#pragma unroll
        for (int e = 0; e < 8; e++) { simp[w][e] = imp[e]; scnt[w][e] = cnt[e]; }
    }
    __syncthreads();
    if (tid < 8) {
        float a = 0.f, b = 0.f;
        for (int ww = 0; ww < 8; ww++) { a += simp[ww][tid]; b += scnt[ww][tid]; }
        g_auxp[blockIdx.x][tid]     = a;
        g_auxp[blockIdx.x][8 + tid] = b;
    }
}

// Fill every output element past the x tensor with the aux scalar. This covers
// both "aux at CN*CD" and "aux at out_size-1" layouts (and any padding) since
// d_out is poisoned before timing.
__global__ void aux_final_k(float* __restrict__ out, int out_size)
{
    if (threadIdx.x == 0 && blockIdx.x == 0) {
        float imp[8], ld[8];
        for (int e = 0; e < 8; e++) { imp[e] = 0.f; ld[e] = 0.f; }
        for (int bk = 0; bk < 32; bk++)
            for (int e = 0; e < 8; e++) { imp[e] += g_auxp[bk][e]; ld[e] += g_auxp[bk][8+e]; }
        float aux = 0.f;
        for (int e = 0; e < 8; e++) aux += (imp[e] * (1.f/CN)) * (ld[e] * (1.f/CNK));
        aux *= (float)CE;
        for (int p = CN*CD; p < out_size; p++) out[p] = aux;
    }
}

// ---------------- host launch sequence ----------------
extern "C" void kernel_launch(void* const* d_in, const int* in_sizes, int n_in,
                              void* d_out, int out_size)
{
    const float* x     = (const float*)d_in[0];
    const float* enc   = (const float*)d_in[1];
    const float* sa_wq = (const float*)d_in[2];  const float* sa_bq = (const float*)d_in[3];
    const float* sa_wk = (const float*)d_in[4];  const float* sa_bk = (const float*)d_in[5];
    const float* sa_wv = (const float*)d_in[6];  const float* sa_bv = (const float*)d_in[7];
    const float* sa_wo = (const float*)d_in[8];  const float* sa_bo = (const float*)d_in[9];
    const float* ca_wq = (const float*)d_in[10]; const float* ca_bq = (const float*)d_in[11];
    const float* ca_wk = (const float*)d_in[12]; const float* ca_bk = (const float*)d_in[13];
    const float* ca_wv = (const float*)d_in[14]; const float* ca_bv = (const float*)d_in[15];
    const float* ca_wo = (const float*)d_in[16]; const float* ca_bo = (const float*)d_in[17];
    const float* n1g   = (const float*)d_in[18]; const float* n1b   = (const float*)d_in[19];
    const float* n2g   = (const float*)d_in[20]; const float* n2b   = (const float*)d_in[21];
    const float* n3g   = (const float*)d_in[22]; const float* n3b   = (const float*)d_in[23];
    const float* rw    = (const float*)d_in[24]; const float* rb    = (const float*)d_in[25];
    const float* ew1   = (const float*)d_in[26]; const float* eb1   = (const float*)d_in[27];
    const float* ew2   = (const float*)d_in[28]; const float* eb2   = (const float*)d_in[29];
    float* out = (float*)d_out;

    float *q, *k, *v, *at, *tmp, *x1, *x2, *h, *ys;
    cudaGetSymbolAddress((void**)&q,   g_q);
    cudaGetSymbolAddress((void**)&k,   g_k);
    cudaGetSymbolAddress((void**)&v,   g_v);
    cudaGetSymbolAddress((void**)&at,  g_attn);
    cudaGetSymbolAddress((void**)&tmp, g_tmp);
    cudaGetSymbolAddress((void**)&x1,  g_x1);
    cudaGetSymbolAddress((void**)&x2,  g_x2);
    cudaGetSymbolAddress((void**)&h,   g_h);
    cudaGetSymbolAddress((void**)&ys,  g_yslot);

    cudaFuncSetAttribute(attn_k, cudaFuncAttributeMaxDynamicSharedMemorySize, ATTN_SMEM);

    dim3 gP(CD/128, CN/128);            // single projection GEMM: (8, 32)
    dim3 gQKV(CD/128, CN/128, 3);       // fused QKV: (8, 32, 3)
    dim3 gAttn(CS/64, CH, CB);          // (32, 16, 2)

    // ---- self attention ----
    qkv_gemm_k<<<gQKV, 256>>>(x, x, sa_wq, sa_wk, sa_wv, sa_bq, sa_bk, sa_bv, q, k, v);
    attn_k<<<gAttn, 256, ATTN_SMEM>>>(q, k, v, at);
    sgemm_k<<<gP, 256>>>(at, sa_wo, sa_bo, tmp, CN, CD, CD);
    add_ln_k<<<CN, 256>>>(x, tmp, n1g, n1b, x1);

    // ---- cross attention ----
    qkv_gemm_k<<<gQKV, 256>>>(x1, enc, ca_wq, ca_wk, ca_wv, ca_bq, ca_bk, ca_bv, q, k, v);
    attn_k<<<gAttn, 256, ATTN_SMEM>>>(q, k, v, at);
    sgemm_k<<<gP, 256>>>(at, ca_wo, ca_bo, tmp, CN, CD, CD);
    add_ln_k<<<CN, 256>>>(x1, tmp, n2g, n2b, x2);

    // ---- MoE ----
    router_k<<<CN/8, 256>>>(x2, rw, rb);
    moe_zero_k<<<1, 32>>>();
    moe_count_k<<<CNK/256, 256>>>();
    moe_off_k<<<1, 1>>>();
    moe_build_k<<<CNK/256, 256>>>();
    moe_gemm_k<1><<<dim3(CF/128, CN/128, CE), 256>>>(x2, ew1, eb1, h,  CF, CD);
    moe_gemm_k<2><<<dim3(CD/128, CN/128, CE), 256>>>(h,  ew2, eb2, ys, CD, CF);
    moe_ln_k<<<CN, 256>>>(x2, n3g, n3b, out);

    // ---- aux loss on final x ----
    aux_partial_k<<<32, 256>>>(out, rw, rb);
    aux_final_k<<<1, 1>>>(out, out_size);
}

// round 6
// speedup vs baseline: 1.2429x; 1.2429x over previous
#include <cuda_runtime.h>
#include <math.h>
#include <stdint.h>

// Problem constants
#define CD  1024      // model dim
#define CH  16        // heads
#define CF  4096      // ffn dim
#define CE  8         // experts
#define CK  2         // top-k
#define CB  2         // batch
#define CS  2048      // seq
#define CN  (CB*CS)   // 4096 tokens
#define CDH 64        // head dim
#define CNK (CN*CK)   // 8192 assignments

// ---------------- scratch (static device globals; no allocation) ----------------
__device__ float g_q[CN*CD];
__device__ float g_k[CN*CD];
__device__ float g_v[CN*CD];
__device__ float g_attn[CN*CD];
__device__ float g_tmp[CN*CD];
__device__ float g_x1[CN*CD];
__device__ float g_x2[CN*CD];
__device__ float g_h[(size_t)CNK*CF];      // 128 MB expert hidden
__device__ float g_yslot[(size_t)CNK*CD];  // 32 MB per-slot expert outputs
__device__ float g_gate[CNK];
__device__ int   g_eid[CNK];
__device__ int   g_cnt[CE];
__device__ int   g_off[CE];
__device__ int   g_cur[CE];
__device__ int   g_list[CNK];
__device__ float g_auxp[32][16];

// ---------------- tf32 helpers ----------------
__device__ __forceinline__ uint32_t f2tf(float f)
{
    uint32_t r;
    asm("cvt.rna.tf32.f32 %0, %1;" : "=r"(r) : "f"(f));
    return r;
}

__device__ __forceinline__ void mma_tf32(float* c, const uint32_t* a, const uint32_t* b)
{
    asm volatile("mma.sync.aligned.m16n8k8.row.col.f32.tf32.tf32.f32 "
                 "{%0,%1,%2,%3}, {%4,%5,%6,%7}, {%8,%9}, {%0,%1,%2,%3};"
                 : "+f"(c[0]), "+f"(c[1]), "+f"(c[2]), "+f"(c[3])
                 : "r"(a[0]), "r"(a[1]), "r"(a[2]), "r"(a[3]),
                   "r"(b[0]), "r"(b[1]));
}

// ---------------- TF32 tensor-core GEMM body ----------------
// Block tile 128x128, k-tile 16, 256 threads = 8 warps (2x4), warp tile 64x32.
// Double-buffered smem; bank-conflict-free strides (A:20, B:136).
// MODE 0: C[M,N] = A[M,K] @ B[K,N] + bias              (dense)
// MODE 1: expert fc1: gather rows of A via g_list, C packed rows, +bias, relu
// MODE 2: expert fc2: A packed rows, C scattered to row g_list[...], (acc+bias)*gate
template<int MODE>
__device__ __forceinline__ void tgemm_body(const float* __restrict__ A,
                                           const float* __restrict__ Bw,
                                           const float* __restrict__ bias,
                                           float* __restrict__ C,
                                           int Meff, int base, int N, int K,
                                           int bm, int bn)
{
    __shared__ uint32_t As[2][128][20];   // [m][k], stride 20 -> conflict-free frag reads
    __shared__ uint32_t Bs[2][16][136];   // [k][n], stride 136 -> conflict-free frag reads

    int tid  = threadIdx.x;
    int w    = tid >> 5, lane = tid & 31;
    int gid  = lane >> 2, tig = lane & 3;
    int wr   = (w & 1) << 6;              // warp row base: 0 / 64
    int wc   = (w >> 1) << 5;             // warp col base: 0/32/64/96

    // A global load mapping: row = tid>>1 (0..127), k-offset 0 or 8
    int ar = tid >> 1;
    int ak = (tid & 1) << 3;
    int r_ld = bm + ar;
    bool avalid = r_ld < Meff;
    const float* Arow;
    if (MODE == 1) {
        int a = avalid ? g_list[base + r_ld] : 0;
        Arow = A + (size_t)(a >> 1) * K;
    } else if (MODE == 2) {
        Arow = A + (size_t)(avalid ? (base + r_ld) : base) * K;
    } else {
        Arow = A + (size_t)(avalid ? r_ld : 0) * K;
    }
    // B global load mapping: k-row = tid>>4 (0..15), col chunk of 8
    int br = tid >> 4;
    int bc = (tid & 15) << 3;
    const float* Bp = Bw + (size_t)br * N + bn + bc;

    float acc[4][4][4];
#pragma unroll
    for (int i = 0; i < 4; i++)
#pragma unroll
        for (int j = 0; j < 4; j++)
#pragma unroll
            for (int q = 0; q < 4; q++) acc[i][j][q] = 0.f;

    int nT = K >> 4;

    { // preload tile 0
        float4 a0 = avalid ? *(const float4*)(Arow + ak)     : make_float4(0.f,0.f,0.f,0.f);
        float4 a1 = avalid ? *(const float4*)(Arow + ak + 4) : make_float4(0.f,0.f,0.f,0.f);
        float4 b0 = *(const float4*)(Bp);
        float4 b1 = *(const float4*)(Bp + 4);
        As[0][ar][ak+0] = f2tf(a0.x); As[0][ar][ak+1] = f2tf(a0.y);
        As[0][ar][ak+2] = f2tf(a0.z); As[0][ar][ak+3] = f2tf(a0.w);
        As[0][ar][ak+4] = f2tf(a1.x); As[0][ar][ak+5] = f2tf(a1.y);
        As[0][ar][ak+6] = f2tf(a1.z); As[0][ar][ak+7] = f2tf(a1.w);
        Bs[0][br][bc+0] = f2tf(b0.x); Bs[0][br][bc+1] = f2tf(b0.y);
        Bs[0][br][bc+2] = f2tf(b0.z); Bs[0][br][bc+3] = f2tf(b0.w);
        Bs[0][br][bc+4] = f2tf(b1.x); Bs[0][br][bc+5] = f2tf(b1.y);
        Bs[0][br][bc+6] = f2tf(b1.z); Bs[0][br][bc+7] = f2tf(b1.w);
    }
    __syncthreads();

    for (int t = 0; t < nT; t++) {
        int cur = t & 1;
        bool pf = (t + 1) < nT;
        float4 av0, av1, bv0, bv1;
        if (pf) {   // issue global loads early; consumed after compute
            const float* Ap = Arow + (t+1)*16 + ak;
            av0 = avalid ? *(const float4*)(Ap)     : make_float4(0.f,0.f,0.f,0.f);
            av1 = avalid ? *(const float4*)(Ap + 4) : make_float4(0.f,0.f,0.f,0.f);
            const float* Bq = Bp + (size_t)(t+1) * 16 * N;
            bv0 = *(const float4*)(Bq);
            bv1 = *(const float4*)(Bq + 4);
        }
#pragma unroll
        for (int ks = 0; ks < 2; ks++) {
            int koff = ks << 3;
            uint32_t af[4][4], bf[4][2];
#pragma unroll
            for (int i = 0; i < 4; i++) {
                int r = wr + i*16 + gid;
                af[i][0] = As[cur][r][koff+tig];
                af[i][1] = As[cur][r+8][koff+tig];
                af[i][2] = As[cur][r][koff+tig+4];
                af[i][3] = As[cur][r+8][koff+tig+4];
            }
#pragma unroll
            for (int j = 0; j < 4; j++) {
                int n = wc + j*8 + gid;
                bf[j][0] = Bs[cur][koff+tig][n];
                bf[j][1] = Bs[cur][koff+tig+4][n];
            }
#pragma unroll
            for (int i = 0; i < 4; i++)
#pragma unroll
                for (int j = 0; j < 4; j++)
                    mma_tf32(acc[i][j], af[i], bf[j]);
        }
        if (pf) {
            int nx = cur ^ 1;
            As[nx][ar][ak+0] = f2tf(av0.x); As[nx][ar][ak+1] = f2tf(av0.y);
            As[nx][ar][ak+2] = f2tf(av0.z); As[nx][ar][ak+3] = f2tf(av0.w);
            As[nx][ar][ak+4] = f2tf(av1.x); As[nx][ar][ak+5] = f2tf(av1.y);
            As[nx][ar][ak+6] = f2tf(av1.z); As[nx][ar][ak+7] = f2tf(av1.w);
            Bs[nx][br][bc+0] = f2tf(bv0.x); Bs[nx][br][bc+1] = f2tf(bv0.y);
            Bs[nx][br][bc+2] = f2tf(bv0.z); Bs[nx][br][bc+3] = f2tf(bv0.w);
            Bs[nx][br][bc+4] = f2tf(bv1.x); Bs[nx][br][bc+5] = f2tf(bv1.y);
            Bs[nx][br][bc+6] = f2tf(bv1.z); Bs[nx][br][bc+7] = f2tf(bv1.w);
        }
        __syncthreads();
    }

    // epilogue: c0,c1 at row gid; c2,c3 at row gid+8; cols tig*2, tig*2+1
#pragma unroll
    for (int i = 0; i < 4; i++) {
#pragma unroll
        for (int half = 0; half < 2; half++) {
            int r = bm + wr + i*16 + gid + half*8;
            if (r >= Meff) continue;
            float* Crow;
            float scale = 1.f;
            if (MODE == 2) {
                int a  = g_list[base + r];
                scale  = g_gate[a];
                Crow   = C + (size_t)a * N;
            } else if (MODE == 1) {
                Crow   = C + (size_t)(base + r) * N;
            } else {
                Crow   = C + (size_t)r * N;
            }
#pragma unroll
            for (int j = 0; j < 4; j++) {
                int col = bn + wc + j*8 + tig*2;
                float v0 = acc[i][j][half*2+0] + bias[col];
                float v1 = acc[i][j][half*2+1] + bias[col+1];
                if (MODE == 1) { v0 = fmaxf(v0, 0.f); v1 = fmaxf(v1, 0.f); }
                if (MODE == 2) { v0 *= scale; v1 *= scale; }
                *(float2*)(Crow + col) = make_float2(v0, v1);
            }
        }
    }
}

// dense single GEMM
__global__ void __launch_bounds__(256, 2) sgemm_k(const float* __restrict__ A,
                                                  const float* __restrict__ Bw,
                                                  const float* __restrict__ bias,
                                                  float* __restrict__ C,
                                                  int M, int N, int K)
{
    tgemm_body<0>(A, Bw, bias, C, M, 0, N, K, blockIdx.y * 128, blockIdx.x * 128);
}

// fused QKV projection: blockIdx.z selects (A, W, bias, C) triple.
__global__ void __launch_bounds__(256, 2) qkv_gemm_k(const float* __restrict__ Aq,
                                                     const float* __restrict__ Akv,
                                                     const float* __restrict__ Wq,
                                                     const float* __restrict__ Wk,
                                                     const float* __restrict__ Wv,
                                                     const float* __restrict__ bq,
                                                     const float* __restrict__ bk,
                                                     const float* __restrict__ bv,
                                                     float* __restrict__ Cq,
                                                     float* __restrict__ Ck,
                                                     float* __restrict__ Cv)
{
    int z = blockIdx.z;
    const float* A  = (z == 0) ? Aq : Akv;
    const float* W  = (z == 0) ? Wq : (z == 1) ? Wk : Wv;
    const float* bb = (z == 0) ? bq : (z == 1) ? bk : bv;
    float*       C  = (z == 0) ? Cq : (z == 1) ? Ck : Cv;
    tgemm_body<0>(A, W, bb, C, CN, 0, CD, CD, blockIdx.y * 128, blockIdx.x * 128);
}

// grouped expert GEMMs (MODE 1 = fc1+relu gather, MODE 2 = fc2 scatter*gate)
template<int MODE>
__global__ void __launch_bounds__(256, 2) moe_gemm_k(const float* __restrict__ A,
                                                     const float* __restrict__ Bw,
                                                     const float* __restrict__ bias,
                                                     float* __restrict__ C,
                                                     int N, int K)
{
    int e = blockIdx.z;
    int Meff = g_cnt[e];
    int base = g_off[e];
    int bm = blockIdx.y * 128;
    if (bm >= Meff) return;
    tgemm_body<MODE>(A, Bw + (size_t)e * K * N, bias + (size_t)e * N, C,
                     Meff, base, N, K, bm, blockIdx.x * 128);
}

// ---------------- flash attention fp32; 64 q-rows x 64 kv per tile ----------------
#define ATTN_SMEM (4*64*68*4)

__global__ void __launch_bounds__(256) attn_k(const float* __restrict__ Q,
                                              const float* __restrict__ Kg,
                                              const float* __restrict__ Vg,
                                              float* __restrict__ O)
{
    extern __shared__ float sm[];
    float* qs = sm;
    float* ks = sm + 64*68;
    float* vs = sm + 2*64*68;
    float* ps = sm + 3*64*68;

    int tid = threadIdx.x;
    int h = blockIdx.y, b = blockIdx.z;
    int q0 = blockIdx.x * 64;
    size_t basebh = ((size_t)b*CS)*CD + (size_t)h*CDH;

    int lrow = tid >> 2;          // 0..63
    int lseg = (tid & 3) << 4;    // 0,16,32,48

    { // load Q tile once
        const float4* src = (const float4*)(Q + basebh + (size_t)(q0+lrow)*CD + lseg);
        float4* dst = (float4*)(qs + lrow*68 + lseg);
#pragma unroll
        for (int i = 0; i < 4; i++) dst[i] = src[i];
    }

    int row = lrow;
    int c0  = lseg;
    float o[16];
#pragma unroll
    for (int i = 0; i < 16; i++) o[i] = 0.f;
    float m = -1e30f, l = 0.f;

    for (int kv0 = 0; kv0 < CS; kv0 += 64) {
        __syncthreads();
        {
            const float4* ksrc = (const float4*)(Kg + basebh + (size_t)(kv0+lrow)*CD + lseg);
            const float4* vsrc = (const float4*)(Vg + basebh + (size_t)(kv0+lrow)*CD + lseg);
            float4* kd = (float4*)(ks + lrow*68 + lseg);
            float4* vd = (float4*)(vs + lrow*68 + lseg);
#pragma unroll
            for (int i = 0; i < 4; i++) { kd[i] = ksrc[i]; vd[i] = vsrc[i]; }
        }
        __syncthreads();

        float s[16];
#pragma unroll
        for (int j = 0; j < 16; j++) s[j] = 0.f;
#pragma unroll 4
        for (int d4 = 0; d4 < 16; d4++) {
            float4 qv = *(const float4*)(qs + row*68 + d4*4);
#pragma unroll
            for (int j = 0; j < 16; j++) {
                float4 kv = *(const float4*)(ks + (c0+j)*68 + d4*4);
                s[j] += qv.x*kv.x + qv.y*kv.y + qv.z*kv.z + qv.w*kv.w;
            }
        }
        float mx = -1e30f;
#pragma unroll
        for (int j = 0; j < 16; j++) { s[j] *= 0.125f; mx = fmaxf(mx, s[j]); }
        mx = fmaxf(mx, __shfl_xor_sync(0xffffffffu, mx, 1));
        mx = fmaxf(mx, __shfl_xor_sync(0xffffffffu, mx, 2));
        float mnew = fmaxf(m, mx);
        float corr = __expf(m - mnew);
        float ls = 0.f;
#pragma unroll
        for (int j = 0; j < 16; j++) { s[j] = __expf(s[j] - mnew); ls += s[j]; }
        ls += __shfl_xor_sync(0xffffffffu, ls, 1);
        ls += __shfl_xor_sync(0xffffffffu, ls, 2);
        l = l*corr + ls;
        m = mnew;
#pragma unroll
        for (int i = 0; i < 16; i++) o[i] *= corr;
#pragma unroll
        for (int j = 0; j < 16; j += 4)
            *(float4*)(ps + row*68 + c0 + j) = make_float4(s[j], s[j+1], s[j+2], s[j+3]);
        __syncthreads();
#pragma unroll 8
        for (int c = 0; c < 64; c++) {
            float p = ps[row*68 + c];
            const float4* vv = (const float4*)(vs + c*68 + c0);
            float4 v0 = vv[0], v1 = vv[1], v2 = vv[2], v3 = vv[3];
            o[0]  += p*v0.x; o[1]  += p*v0.y; o[2]  += p*v0.z; o[3]  += p*v0.w;
            o[4]  += p*v1.x; o[5]  += p*v1.y; o[6]  += p*v1.z; o[7]  += p*v1.w;
            o[8]  += p*v2.x; o[9]  += p*v2.y; o[10] += p*v2.z; o[11] += p*v2.w;
            o[12] += p*v3.x; o[13] += p*v3.y; o[14] += p*v3.z; o[15] += p*v3.w;
        }
    }
    float inv = 1.f / l;
    float* op = O + basebh + (size_t)(q0+row)*CD + c0;
#pragma unroll
    for (int j = 0; j < 16; j += 4)
        *(float4*)(op + j) = make_float4(o[j]*inv, o[j+1]*inv, o[j+2]*inv, o[j+3]*inv);
}

// ---------------- block reduce helper ----------------
__device__ __forceinline__ float blk_sum(float v, float* red)
{
    int lane = threadIdx.x & 31, w = threadIdx.x >> 5;
#pragma unroll
    for (int o = 16; o; o >>= 1) v += __shfl_xor_sync(0xffffffffu, v, o);
    if (lane == 0) red[w] = v;
    __syncthreads();
    if (threadIdx.x == 0) {
        float t = 0.f;
        for (int i = 0; i < 8; i++) t += red[i];
        red[8] = t;
    }
    __syncthreads();
    float r = red[8];
    __syncthreads();
    return r;
}

// ---------------- residual add + layernorm (row = 1024) ----------------
__global__ void __launch_bounds__(256) add_ln_k(const float* __restrict__ a,
                                                const float* __restrict__ b,
                                                const float* __restrict__ gg,
                                                const float* __restrict__ bb,
                                                float* __restrict__ out)
{
    __shared__ float red[9];
    size_t base = (size_t)blockIdx.x * CD;
    int tid = threadIdx.x;
    float v[4];
    float s = 0.f;
#pragma unroll
    for (int i = 0; i < 4; i++) { int c = tid + (i<<8); float t = a[base+c] + b[base+c]; v[i] = t; s += t; }
    float mean = blk_sum(s, red) * (1.f/CD);
    float qq = 0.f;
#pragma unroll
    for (int i = 0; i < 4; i++) { float d = v[i]-mean; qq += d*d; }
    float var = blk_sum(qq, red) * (1.f/CD);
    float rstd = rsqrtf(var + 1e-5f);
#pragma unroll
    for (int i = 0; i < 4; i++) { int c = tid + (i<<8); out[base+c] = (v[i]-mean)*rstd*gg[c] + bb[c]; }
}

// combine the 2 expert slots + residual + LN3, write final x into d_out
__global__ void __launch_bounds__(256) moe_ln_k(const float* __restrict__ a,
                                                const float* __restrict__ gg,
                                                const float* __restrict__ bb,
                                                float* __restrict__ out)
{
    __shared__ float red[9];
    int rowid = blockIdx.x;
    size_t base = (size_t)rowid * CD;
    const float* y0 = g_yslot + (size_t)(2*rowid) * CD;
    const float* y1 = y0 + CD;
    int tid = threadIdx.x;
    float v[4];
    float s = 0.f;
#pragma unroll
    for (int i = 0; i < 4; i++) { int c = tid + (i<<8); float t = a[base+c] + y0[c] + y1[c]; v[i] = t; s += t; }
    float mean = blk_sum(s, red) * (1.f/CD);
    float qq = 0.f;
#pragma unroll
    for (int i = 0; i < 4; i++) { float d = v[i]-mean; qq += d*d; }
    float var = blk_sum(qq, red) * (1.f/CD);
    float rstd = rsqrtf(var + 1e-5f);
#pragma unroll
    for (int i = 0; i < 4; i++) { int c = tid + (i<<8); out[base+c] = (v[i]-mean)*rstd*gg[c] + bb[c]; }
}

// ---------------- router: softmax over 8 logits, top-2, renormalized gates ----------------
__global__ void __launch_bounds__(256) router_k(const float* __restrict__ x,
                                                const float* __restrict__ rw,
                                                const float* __restrict__ rb)
{
    int gw = (blockIdx.x * blockDim.x + threadIdx.x) >> 5;
    int lane = threadIdx.x & 31;
    if (gw >= CN) return;
    const float* xr = x + (size_t)gw * CD;
    float acc[8];
#pragma unroll
    for (int e = 0; e < 8; e++) acc[e] = 0.f;
    for (int d = lane; d < CD; d += 32) {
        float xv = xr[d];
        const float4* wp = (const float4*)(rw + d*CE);
        float4 w0 = wp[0], w1 = wp[1];
        acc[0] += xv*w0.x; acc[1] += xv*w0.y; acc[2] += xv*w0.z; acc[3] += xv*w0.w;
        acc[4] += xv*w1.x; acc[5] += xv*w1.y; acc[6] += xv*w1.z; acc[7] += xv*w1.w;
    }
#pragma unroll
    for (int e = 0; e < 8; e++)
#pragma unroll
        for (int o = 16; o; o >>= 1) acc[e] += __shfl_xor_sync(0xffffffffu, acc[e], o);
    if (lane == 0) {
        float p[8];
        float mx = -1e30f;
#pragma unroll
        for (int e = 0; e < 8; e++) { p[e] = acc[e] + rb[e]; mx = fmaxf(mx, p[e]); }
        float se = 0.f;
#pragma unroll
        for (int e = 0; e < 8; e++) { p[e] = __expf(p[e]-mx); se += p[e]; }
        float inv = 1.f/se;
#pragma unroll
        for (int e = 0; e < 8; e++) p[e] *= inv;
        int i1 = 0;
#pragma unroll
        for (int e = 1; e < 8; e++) if (p[e] > p[i1]) i1 = e;
        int i2 = -1;
#pragma unroll
        for (int e = 0; e < 8; e++) if (e != i1 && (i2 < 0 || p[e] > p[i2])) i2 = e;
        float s2 = p[i1] + p[i2];
        g_eid[2*gw]   = i1;  g_eid[2*gw+1]   = i2;
        g_gate[2*gw]  = p[i1]/s2; g_gate[2*gw+1] = p[i2]/s2;
    }
}

// ---------------- MoE dispatch bookkeeping ----------------
__global__ void moe_zero_k() { if (threadIdx.x < CE) g_cnt[threadIdx.x] = 0; }
__global__ void moe_count_k() {
    int i = blockIdx.x * blockDim.x + threadIdx.x;
    if (i < CNK) atomicAdd(&g_cnt[g_eid[i]], 1);
}
__global__ void moe_off_k() {
    if (threadIdx.x == 0) {
        int s = 0;
        for (int e = 0; e < CE; e++) { g_off[e] = s; g_cur[e] = s; s += g_cnt[e]; }
    }
}
__global__ void moe_build_k() {
    int i = blockIdx.x * blockDim.x + threadIdx.x;
    if (i < CNK) {
        int pos = atomicAdd(&g_cur[g_eid[i]], 1);
        g_list[pos] = i;
    }
}

// ---------------- aux loss: two-stage deterministic reduction ----------------
__global__ void __launch_bounds__(256) aux_partial_k(const float* __restrict__ x,
                                                     const float* __restrict__ rw,
                                                     const float* __restrict__ rb)
{
    __shared__ float simp[8][8];
    __shared__ float scnt[8][8];
    int tid = threadIdx.x, lane = tid & 31, w = tid >> 5;
    float imp[8], cnt[8];
#pragma unroll
    for (int e = 0; e < 8; e++) { imp[e] = 0.f; cnt[e] = 0.f; }
    for (int i = 0; i < 16; i++) {
        int t = blockIdx.x * 128 + w * 16 + i;
        const float* xr = x + (size_t)t * CD;
        float acc[8];
#pragma unroll
        for (int e = 0; e < 8; e++) acc[e] = 0.f;
        for (int d = lane; d < CD; d += 32) {
            float xv = xr[d];
            const float4* wp = (const float4*)(rw + d*CE);
            float4 w0 = wp[0], w1 = wp[1];
            acc[0] += xv*w0.x; acc[1] += xv*w0.y; acc[2] += xv*w0.z; acc[3] += xv*w0.w;
            acc[4] += xv*w1.x; acc[5] += xv*w1.y; acc[6] += xv*w1.z; acc[7] += xv*w1.w;
        }
#pragma unroll
        for (int e = 0; e < 8; e++)
#pragma unroll
            for (int o = 16; o; o >>= 1) acc[e] += __shfl_xor_sync(0xffffffffu, acc[e], o);
        if (lane == 0) {
            float p[8];
            float mx = -1e30f;
#pragma unroll
            for (int e = 0; e < 8; e++) { p[e] = acc[e] + rb[e]; mx = fmaxf(mx, p[e]); }
            float se = 0.f;
#pragma unroll
            for (int e = 0; e < 8; e++) { p[e] = __expf(p[e]-mx); se += p[e]; }
            float inv = 1.f/se;
#pragma unroll
            for (int e = 0; e < 8; e++) { p[e] *= inv; imp[e] += p[e]; }
            int i1 = 0;
#pragma unroll
            for (int e = 1; e < 8; e++) if (p[e] > p[i1]) i1 = e;
            int i2 = -1;
#pragma unroll
            for (int e = 0; e < 8; e++) if (e != i1 && (i2 < 0 || p[e] > p[i2])) i2 = e;
            cnt[i1] += 1.f; cnt[i2] += 1.f;
        }
    }
    if (lane == 0) {
#pragma unroll
        for (int e = 0; e < 8; e++) { simp[w][e] = imp[e]; scnt[w][e] = cnt[e]; }
    }
    __syncthreads();
    if (tid < 8) {
        float a = 0.f, b = 0.f;
        for (int ww = 0; ww < 8; ww++) { a += simp[ww][tid]; b += scnt[ww][tid]; }
        g_auxp[blockIdx.x][tid]     = a;
        g_auxp[blockIdx.x][8 + tid] = b;
    }
}

// Fill every output element past the x tensor with the aux scalar.
__global__ void aux_final_k(float* __restrict__ out, int out_size)
{
    if (threadIdx.x == 0 && blockIdx.x == 0) {
        float imp[8], ld[8];
        for (int e = 0; e < 8; e++) { imp[e] = 0.f; ld[e] = 0.f; }
        for (int bk = 0; bk < 32; bk++)
            for (int e = 0; e < 8; e++) { imp[e] += g_auxp[bk][e]; ld[e] += g_auxp[bk][8+e]; }
        float aux = 0.f;
        for (int e = 0; e < 8; e++) aux += (imp[e] * (1.f/CN)) * (ld[e] * (1.f/CNK));
        aux *= (float)CE;
        for (int p = CN*CD; p < out_size; p++) out[p] = aux;
    }
}

// ---------------- host launch sequence ----------------
extern "C" void kernel_launch(void* const* d_in, const int* in_sizes, int n_in,
                              void* d_out, int out_size)
{
    const float* x     = (const float*)d_in[0];
    const float* enc   = (const float*)d_in[1];
    const float* sa_wq = (const float*)d_in[2];  const float* sa_bq = (const float*)d_in[3];
    const float* sa_wk = (const float*)d_in[4];  const float* sa_bk = (const float*)d_in[5];
    const float* sa_wv = (const float*)d_in[6];  const float* sa_bv = (const float*)d_in[7];
    const float* sa_wo = (const float*)d_in[8];  const float* sa_bo = (const float*)d_in[9];
    const float* ca_wq = (const float*)d_in[10]; const float* ca_bq = (const float*)d_in[11];
    const float* ca_wk = (const float*)d_in[12]; const float* ca_bk = (const float*)d_in[13];
    const float* ca_wv = (const float*)d_in[14]; const float* ca_bv = (const float*)d_in[15];
    const float* ca_wo = (const float*)d_in[16]; const float* ca_bo = (const float*)d_in[17];
    const float* n1g   = (const float*)d_in[18]; const float* n1b   = (const float*)d_in[19];
    const float* n2g   = (const float*)d_in[20]; const float* n2b   = (const float*)d_in[21];
    const float* n3g   = (const float*)d_in[22]; const float* n3b   = (const float*)d_in[23];
    const float* rw    = (const float*)d_in[24]; const float* rb    = (const float*)d_in[25];
    const float* ew1   = (const float*)d_in[26]; const float* eb1   = (const float*)d_in[27];
    const float* ew2   = (const float*)d_in[28]; const float* eb2   = (const float*)d_in[29];
    float* out = (float*)d_out;

    float *q, *k, *v, *at, *tmp, *x1, *x2, *h, *ys;
    cudaGetSymbolAddress((void**)&q,   g_q);
    cudaGetSymbolAddress((void**)&k,   g_k);
    cudaGetSymbolAddress((void**)&v,   g_v);
    cudaGetSymbolAddress((void**)&at,  g_attn);
    cudaGetSymbolAddress((void**)&tmp, g_tmp);
    cudaGetSymbolAddress((void**)&x1,  g_x1);
    cudaGetSymbolAddress((void**)&x2,  g_x2);
    cudaGetSymbolAddress((void**)&h,   g_h);
    cudaGetSymbolAddress((void**)&ys,  g_yslot);

    cudaFuncSetAttribute(attn_k, cudaFuncAttributeMaxDynamicSharedMemorySize, ATTN_SMEM);

    dim3 gP(CD/128, CN/128);            // single projection GEMM: (8, 32)
    dim3 gQKV(CD/128, CN/128, 3);       // fused QKV: (8, 32, 3)
    dim3 gAttn(CS/64, CH, CB);          // (32, 16, 2)

    // ---- self attention ----
    qkv_gemm_k<<<gQKV, 256>>>(x, x, sa_wq, sa_wk, sa_wv, sa_bq, sa_bk, sa_bv, q, k, v);
    attn_k<<<gAttn, 256, ATTN_SMEM>>>(q, k, v, at);
    sgemm_k<<<gP, 256>>>(at, sa_wo, sa_bo, tmp, CN, CD, CD);
    add_ln_k<<<CN, 256>>>(x, tmp, n1g, n1b, x1);

    // ---- cross attention ----
    qkv_gemm_k<<<gQKV, 256>>>(x1, enc, ca_wq, ca_wk, ca_wv, ca_bq, ca_bk, ca_bv, q, k, v);
    attn_k<<<gAttn, 256, ATTN_SMEM>>>(q, k, v, at);
    sgemm_k<<<gP, 256>>>(at, ca_wo, ca_bo, tmp, CN, CD, CD);
    add_ln_k<<<CN, 256>>>(x1, tmp, n2g, n2b, x2);

    // ---- MoE ----
    router_k<<<CN/8, 256>>>(x2, rw, rb);
    moe_zero_k<<<1, 32>>>();
    moe_count_k<<<CNK/256, 256>>>();
    moe_off_k<<<1, 1>>>();
    moe_build_k<<<CNK/256, 256>>>();
    moe_gemm_k<1><<<dim3(CF/128, CN/128, CE), 256>>>(x2, ew1, eb1, h,  CF, CD);
    moe_gemm_k<2><<<dim3(CD/128, CN/128, CE), 256>>>(h,  ew2, eb2, ys, CD, CF);
    moe_ln_k<<<CN, 256>>>(x2, n3g, n3b, out);

    // ---- aux loss on final x ----
    aux_partial_k<<<32, 256>>>(out, rw, rb);
    aux_final_k<<<1, 1>>>(out, out_size);
}

// round 8
// speedup vs baseline: 5.7971x; 4.6642x over previous
#include <cuda_runtime.h>
#include <math.h>
#include <stdint.h>

// Problem constants
#define CD  1024      // model dim
#define CH  16        // heads
#define CF  4096      // ffn dim
#define CE  8         // experts
#define CK  2         // top-k
#define CB  2         // batch
#define CS  2048      // seq
#define CN  (CB*CS)   // 4096 tokens
#define CDH 64        // head dim
#define CNK (CN*CK)   // 8192 assignments

// ---------------- scratch (static device globals; no allocation) ----------------
__device__ float g_q[CN*CD];
__device__ float g_k[CN*CD];
__device__ float g_v[CN*CD];
__device__ float g_attn[CN*CD];
__device__ float g_tmp[CN*CD];
__device__ float g_x1[CN*CD];
__device__ float g_x2[CN*CD];
__device__ float g_h[(size_t)CNK*CF];      // 128 MB expert hidden
__device__ float g_yslot[(size_t)CNK*CD];  // 32 MB per-slot expert outputs
__device__ float g_gate[CNK];
__device__ int   g_eid[CNK];
__device__ int   g_cnt[CE];
__device__ int   g_off[CE];
__device__ int   g_cur[CE];
__device__ int   g_list[CNK];
__device__ float g_auxp[32][16];

// ---------------- tf32 helpers ----------------
__device__ __forceinline__ uint32_t f2tf(float f)
{
    uint32_t r;
    asm("cvt.rna.tf32.f32 %0, %1;" : "=r"(r) : "f"(f));
    return r;
}

__device__ __forceinline__ void mma_tf32(float* c, const uint32_t* a, const uint32_t* b)
{
    asm volatile("mma.sync.aligned.m16n8k8.row.col.f32.tf32.tf32.f32 "
                 "{%0,%1,%2,%3}, {%4,%5,%6,%7}, {%8,%9}, {%0,%1,%2,%3};"
                 : "+f"(c[0]), "+f"(c[1]), "+f"(c[2]), "+f"(c[3])
                 : "r"(a[0]), "r"(a[1]), "r"(a[2]), "r"(a[3]),
                   "r"(b[0]), "r"(b[1]));
}

// ---------------- TF32 tensor-core GEMM body ----------------
// Block tile 128x128, k-tile 16, 256 threads = 8 warps (2x4), warp tile 64x32.
// Double-buffered smem; bank-conflict-free strides (A:20, B:136). STS.128 fills.
// MODE 0: C[M,N] = A[M,K] @ B[K,N] + bias              (dense)
// MODE 1: expert fc1: gather rows of A via g_list, C packed rows, +bias, relu
// MODE 2: expert fc2: A packed rows, C scattered to row g_list[...], (acc+bias)*gate
template<int MODE>
__device__ __forceinline__ void tgemm_body(const float* __restrict__ A,
                                           const float* __restrict__ Bw,
                                           const float* __restrict__ bias,
                                           float* __restrict__ C,
                                           int Meff, int base, int N, int K,
                                           int bm, int bn)
{
    __shared__ uint32_t As[2][128][20];   // [m][k], stride 20 -> conflict-free frag reads
    __shared__ uint32_t Bs[2][16][136];   // [k][n], stride 136 -> conflict-free frag reads

    int tid  = threadIdx.x;
    int w    = tid >> 5, lane = tid & 31;
    int gid  = lane >> 2, tig = lane & 3;
    int wr   = (w & 1) << 6;              // warp row base: 0 / 64
    int wc   = (w >> 1) << 5;             // warp col base: 0/32/64/96

    // A global load mapping: row = tid>>1 (0..127), k-offset 0 or 8
    int ar = tid >> 1;
    int ak = (tid & 1) << 3;
    int r_ld = bm + ar;
    bool avalid = r_ld < Meff;
    const float* Arow;
    if (MODE == 1) {
        int a = avalid ? g_list[base + r_ld] : 0;
        Arow = A + (size_t)(a >> 1) * K;
    } else if (MODE == 2) {
        Arow = A + (size_t)(avalid ? (base + r_ld) : base) * K;
    } else {
        Arow = A + (size_t)(avalid ? r_ld : 0) * K;
    }
    // B global load mapping: k-row = tid>>4 (0..15), col chunk of 8
    int br = tid >> 4;
    int bc = (tid & 15) << 3;
    const float* Bp = Bw + (size_t)br * N + bn + bc;

    float acc[4][4][4];
#pragma unroll
    for (int i = 0; i < 4; i++)
#pragma unroll
        for (int j = 0; j < 4; j++)
#pragma unroll
            for (int q = 0; q < 4; q++) acc[i][j][q] = 0.f;

    int nT = K >> 4;

    { // preload tile 0
        float4 a0 = avalid ? *(const float4*)(Arow + ak)     : make_float4(0.f,0.f,0.f,0.f);
        float4 a1 = avalid ? *(const float4*)(Arow + ak + 4) : make_float4(0.f,0.f,0.f,0.f);
        float4 b0 = *(const float4*)(Bp);
        float4 b1 = *(const float4*)(Bp + 4);
        *(uint4*)&As[0][ar][ak]   = make_uint4(f2tf(a0.x), f2tf(a0.y), f2tf(a0.z), f2tf(a0.w));
        *(uint4*)&As[0][ar][ak+4] = make_uint4(f2tf(a1.x), f2tf(a1.y), f2tf(a1.z), f2tf(a1.w));
        *(uint4*)&Bs[0][br][bc]   = make_uint4(f2tf(b0.x), f2tf(b0.y), f2tf(b0.z), f2tf(b0.w));
        *(uint4*)&Bs[0][br][bc+4] = make_uint4(f2tf(b1.x), f2tf(b1.y), f2tf(b1.z), f2tf(b1.w));
    }
    __syncthreads();

    for (int t = 0; t < nT; t++) {
        int cur = t & 1;
        bool pf = (t + 1) < nT;
        float4 av0, av1, bv0, bv1;
        if (pf) {   // issue global loads early; consumed after compute
            const float* Ap = Arow + (t+1)*16 + ak;
            av0 = avalid ? *(const float4*)(Ap)     : make_float4(0.f,0.f,0.f,0.f);
            av1 = avalid ? *(const float4*)(Ap + 4) : make_float4(0.f,0.f,0.f,0.f);
            const float* Bq = Bp + (size_t)(t+1) * 16 * N;
            bv0 = *(const float4*)(Bq);
            bv1 = *(const float4*)(Bq + 4);
        }
#pragma unroll
        for (int ks = 0; ks < 2; ks++) {
            int koff = ks << 3;
            uint32_t af[4][4], bf[4][2];
#pragma unroll
            for (int i = 0; i < 4; i++) {
                int r = wr + i*16 + gid;
                af[i][0] = As[cur][r][koff+tig];
                af[i][1] = As[cur][r+8][koff+tig];
                af[i][2] = As[cur][r][koff+tig+4];
                af[i][3] = As[cur][r+8][koff+tig+4];
            }
#pragma unroll
            for (int j = 0; j < 4; j++) {
                int n = wc + j*8 + gid;
                bf[j][0] = Bs[cur][koff+tig][n];
                bf[j][1] = Bs[cur][koff+tig+4][n];
            }
#pragma unroll
            for (int i = 0; i < 4; i++)
#pragma unroll
                for (int j = 0; j < 4; j++)
                    mma_tf32(acc[i][j], af[i], bf[j]);
        }
        if (pf) {
            int nx = cur ^ 1;
            *(uint4*)&As[nx][ar][ak]   = make_uint4(f2tf(av0.x), f2tf(av0.y), f2tf(av0.z), f2tf(av0.w));
            *(uint4*)&As[nx][ar][ak+4] = make_uint4(f2tf(av1.x), f2tf(av1.y), f2tf(av1.z), f2tf(av1.w));
            *(uint4*)&Bs[nx][br][bc]   = make_uint4(f2tf(bv0.x), f2tf(bv0.y), f2tf(bv0.z), f2tf(bv0.w));
            *(uint4*)&Bs[nx][br][bc+4] = make_uint4(f2tf(bv1.x), f2tf(bv1.y), f2tf(bv1.z), f2tf(bv1.w));
        }
        __syncthreads();
    }

    // epilogue: c0,c1 at row gid; c2,c3 at row gid+8; cols tig*2, tig*2+1
#pragma unroll
    for (int i = 0; i < 4; i++) {
#pragma unroll
        for (int half = 0; half < 2; half++) {
            int r = bm + wr + i*16 + gid + half*8;
            if (r >= Meff) continue;
            float* Crow;
            float scale = 1.f;
            if (MODE == 2) {
                int a  = g_list[base + r];
                scale  = g_gate[a];
                Crow   = C + (size_t)a * N;
            } else if (MODE == 1) {
                Crow   = C + (size_t)(base + r) * N;
            } else {
                Crow   = C + (size_t)r * N;
            }
#pragma unroll
            for (int j = 0; j < 4; j++) {
                int col = bn + wc + j*8 + tig*2;
                float v0 = acc[i][j][half*2+0] + bias[col];
                float v1 = acc[i][j][half*2+1] + bias[col+1];
                if (MODE == 1) { v0 = fmaxf(v0, 0.f); v1 = fmaxf(v1, 0.f); }
                if (MODE == 2) { v0 *= scale; v1 *= scale; }
                *(float2*)(Crow + col) = make_float2(v0, v1);
            }
        }
    }
}

// dense single GEMM
__global__ void __launch_bounds__(256, 2) sgemm_k(const float* __restrict__ A,
                                                  const float* __restrict__ Bw,
                                                  const float* __restrict__ bias,
                                                  float* __restrict__ C,
                                                  int M, int N, int K)
{
    tgemm_body<0>(A, Bw, bias, C, M, 0, N, K, blockIdx.y * 128, blockIdx.x * 128);
}

// fused QKV projection: blockIdx.z selects (A, W, bias, C) triple.
__global__ void __launch_bounds__(256, 2) qkv_gemm_k(const float* __restrict__ Aq,
                                                     const float* __restrict__ Akv,
                                                     const float* __restrict__ Wq,
                                                     const float* __restrict__ Wk,
                                                     const float* __restrict__ Wv,
                                                     const float* __restrict__ bq,
                                                     const float* __restrict__ bk,
                                                     const float* __restrict__ bv,
                                                     float* __restrict__ Cq,
                                                     float* __restrict__ Ck,
                                                     float* __restrict__ Cv)
{
    int z = blockIdx.z;
    const float* A  = (z == 0) ? Aq : Akv;
    const float* W  = (z == 0) ? Wq : (z == 1) ? Wk : Wv;
    const float* bb = (z == 0) ? bq : (z == 1) ? bk : bv;
    float*       C  = (z == 0) ? Cq : (z == 1) ? Ck : Cv;
    tgemm_body<0>(A, W, bb, C, CN, 0, CD, CD, blockIdx.y * 128, blockIdx.x * 128);
}

// grouped expert GEMMs (MODE 1 = fc1+relu gather, MODE 2 = fc2 scatter*gate)
template<int MODE>
__global__ void __launch_bounds__(256, 2) moe_gemm_k(const float* __restrict__ A,
                                                     const float* __restrict__ Bw,
                                                     const float* __restrict__ bias,
                                                     float* __restrict__ C,
                                                     int N, int K)
{
    int e = blockIdx.z;
    int Meff = g_cnt[e];
    int base = g_off[e];
    int bm = blockIdx.y * 128;
    if (bm >= Meff) return;
    tgemm_body<MODE>(A, Bw + (size_t)e * K * N, bias + (size_t)e * N, C,
                     Meff, base, N, K, bm, blockIdx.x * 128);
}

// ---------------- TF32 tensor-core flash attention ----------------
// Block: 128 q-rows, 8 warps x 16 rows each; kv tiles of 64.
// smem rows stride 72 words -> conflict-free fragment access patterns.
// Q pre-scaled by 1/sqrt(DH) at fragment load. P re-layout via per-warp smem.
#define AT_SMEM ((64*72 + 64*72 + 128*72)*4)

__global__ void __launch_bounds__(256, 2) attn_tc_k(const float* __restrict__ Q,
                                                    const float* __restrict__ Kg,
                                                    const float* __restrict__ Vg,
                                                    float* __restrict__ O)
{
    extern __shared__ uint32_t smw[];
    uint32_t* ks = smw;               // [64][72]
    uint32_t* vs = smw + 64*72;       // [64][72]
    uint32_t* ps = smw + 2*64*72;     // [128][72]

    int tid  = threadIdx.x;
    int w    = tid >> 5, lane = tid & 31;
    int gid  = lane >> 2, tig = lane & 3;
    int h = blockIdx.y, b = blockIdx.z;
    int q0 = blockIdx.x * 128;
    size_t basebh = ((size_t)b*CS)*CD + (size_t)h*CDH;
    int wbase = w << 4;               // warp's q-row base within block

    // Q fragments for this warp's 16 rows (scaled by 0.125 = 1/sqrt(64))
    uint32_t qa[8][4];
    {
        const float* Qb = Q + basebh + (size_t)(q0 + wbase) * CD;
#pragma unroll
        for (int kk = 0; kk < 8; kk++) {
            int c = kk*8 + tig;
            qa[kk][0] = f2tf(0.125f * Qb[(size_t)gid*CD + c]);
            qa[kk][1] = f2tf(0.125f * Qb[(size_t)(gid+8)*CD + c]);
            qa[kk][2] = f2tf(0.125f * Qb[(size_t)gid*CD + c + 4]);
            qa[kk][3] = f2tf(0.125f * Qb[(size_t)(gid+8)*CD + c + 4]);
        }
    }

    float m0 = -1e30f, m1 = -1e30f, l0 = 0.f, l1 = 0.f;
    float oacc[8][4];
#pragma unroll
    for (int j = 0; j < 8; j++)
#pragma unroll
        for (int q = 0; q < 4; q++) oacc[j][q] = 0.f;

    int lr = tid >> 4;              // 0..15
    int lc = (tid & 15) << 2;       // 0..60

    for (int kv0 = 0; kv0 < CS; kv0 += 64) {
        __syncthreads();   // all warps done reading ks/vs of previous tile
        {
            const float* Kb = Kg + basebh + (size_t)kv0 * CD;
            const float* Vb = Vg + basebh + (size_t)kv0 * CD;
#pragma unroll
            for (int rr = lr; rr < 64; rr += 16) {
                float4 k4 = *(const float4*)(Kb + (size_t)rr*CD + lc);
                float4 v4 = *(const float4*)(Vb + (size_t)rr*CD + lc);
                *(uint4*)&ks[rr*72 + lc] = make_uint4(f2tf(k4.x), f2tf(k4.y), f2tf(k4.z), f2tf(k4.w));
                *(uint4*)&vs[rr*72 + lc] = make_uint4(f2tf(v4.x), f2tf(v4.y), f2tf(v4.z), f2tf(v4.w));
            }
        }
        __syncthreads();

        // S = Q K^T  (16 x 64 per warp)
        float sacc[8][4];
#pragma unroll
        for (int j = 0; j < 8; j++)
#pragma unroll
            for (int q = 0; q < 4; q++) sacc[j][q] = 0.f;
#pragma unroll
        for (int kk = 0; kk < 8; kk++) {
            int koff = kk << 3;
#pragma unroll
            for (int j = 0; j < 8; j++) {
                uint32_t bq[2];
                int n = j*8 + gid;
                bq[0] = ks[n*72 + koff + tig];
                bq[1] = ks[n*72 + koff + tig + 4];
                mma_tf32(sacc[j], qa[kk], bq);
            }
        }

        // online softmax (two rows per lane: r0=gid, r1=gid+8)
        float mx0 = -1e30f, mx1 = -1e30f;
#pragma unroll
        for (int j = 0; j < 8; j++) {
            mx0 = fmaxf(mx0, fmaxf(sacc[j][0], sacc[j][1]));
            mx1 = fmaxf(mx1, fmaxf(sacc[j][2], sacc[j][3]));
        }
        mx0 = fmaxf(mx0, __shfl_xor_sync(0xffffffffu, mx0, 1));
        mx0 = fmaxf(mx0, __shfl_xor_sync(0xffffffffu, mx0, 2));
        mx1 = fmaxf(mx1, __shfl_xor_sync(0xffffffffu, mx1, 1));
        mx1 = fmaxf(mx1, __shfl_xor_sync(0xffffffffu, mx1, 2));
        float nm0 = fmaxf(m0, mx0), nm1 = fmaxf(m1, mx1);
        float cr0 = __expf(m0 - nm0), cr1 = __expf(m1 - nm1);
        float ls0 = 0.f, ls1 = 0.f;
        int pr0 = (wbase + gid) * 72;
        int pr1 = (wbase + gid + 8) * 72;
#pragma unroll
        for (int j = 0; j < 8; j++) {
            float p0 = __expf(sacc[j][0] - nm0);
            float p1 = __expf(sacc[j][1] - nm0);
            float p2 = __expf(sacc[j][2] - nm1);
            float p3 = __expf(sacc[j][3] - nm1);
            ls0 += p0 + p1;
            ls1 += p2 + p3;
            int c = j*8 + 2*tig;
            *(uint2*)&ps[pr0 + c] = make_uint2(f2tf(p0), f2tf(p1));
            *(uint2*)&ps[pr1 + c] = make_uint2(f2tf(p2), f2tf(p3));
        }
        ls0 += __shfl_xor_sync(0xffffffffu, ls0, 1);
        ls0 += __shfl_xor_sync(0xffffffffu, ls0, 2);
        ls1 += __shfl_xor_sync(0xffffffffu, ls1, 1);
        ls1 += __shfl_xor_sync(0xffffffffu, ls1, 2);
        l0 = l0*cr0 + ls0;  m0 = nm0;
        l1 = l1*cr1 + ls1;  m1 = nm1;
#pragma unroll
        for (int j = 0; j < 8; j++) {
            oacc[j][0] *= cr0; oacc[j][1] *= cr0;
            oacc[j][2] *= cr1; oacc[j][3] *= cr1;
        }
        __syncwarp();   // ps rows of this warp visible to all its lanes

        // O += P V  (16 x 64 per warp)
#pragma unroll
        for (int kk = 0; kk < 8; kk++) {
            int koff = kk << 3;
            uint32_t pa[4];
            pa[0] = ps[pr0 + koff + tig];
            pa[1] = ps[pr1 + koff + tig];
            pa[2] = ps[pr0 + koff + tig + 4];
            pa[3] = ps[pr1 + koff + tig + 4];
#pragma unroll
            for (int j = 0; j < 8; j++) {
                uint32_t vb[2];
                int n = j*8 + gid;
                vb[0] = vs[(koff + tig)*72 + n];
                vb[1] = vs[(koff + tig + 4)*72 + n];
                mma_tf32(oacc[j], pa, vb);
            }
        }
        __syncwarp();   // all lanes done reading ps before next overwrite
    }

    float inv0 = 1.f / l0, inv1 = 1.f / l1;
    float* Ob = O + basebh + (size_t)(q0 + wbase) * CD;
#pragma unroll
    for (int j = 0; j < 8; j++) {
        int c = j*8 + 2*tig;
        *(float2*)(Ob + (size_t)gid*CD + c)     = make_float2(oacc[j][0]*inv0, oacc[j][1]*inv0);
        *(float2*)(Ob + (size_t)(gid+8)*CD + c) = make_float2(oacc[j][2]*inv1, oacc[j][3]*inv1);
    }
}

// ---------------- block reduce helper ----------------
__device__ __forceinline__ float blk_sum(float v, float* red)
{
    int lane = threadIdx.x & 31, w = threadIdx.x >> 5;
#pragma unroll
    for (int o = 16; o; o >>= 1) v += __shfl_xor_sync(0xffffffffu, v, o);
    if (lane == 0) red[w] = v;
    __syncthreads();
    if (threadIdx.x == 0) {
        float t = 0.f;
        for (int i = 0; i < 8; i++) t += red[i];
        red[8] = t;
    }
    __syncthreads();
    float r = red[8];
    __syncthreads();
    return r;
}

// ---------------- residual add + layernorm (row = 1024) ----------------
__global__ void __launch_bounds__(256) add_ln_k(const float* __restrict__ a,
                                                const float* __restrict__ b,
                                                const float* __restrict__ gg,
                                                const float* __restrict__ bb,
                                                float* __restrict__ out)
{
    __shared__ float red[9];
    size_t base = (size_t)blockIdx.x * CD;
    int tid = threadIdx.x;
    float v[4];
    float s = 0.f;
#pragma unroll
    for (int i = 0; i < 4; i++) { int c = tid + (i<<8); float t = a[base+c] + b[base+c]; v[i] = t; s += t; }
    float mean = blk_sum(s, red) * (1.f/CD);
    float qq = 0.f;
#pragma unroll
    for (int i = 0; i < 4; i++) { float d = v[i]-mean; qq += d*d; }
    float var = blk_sum(qq, red) * (1.f/CD);
    float rstd = rsqrtf(var + 1e-5f);
#pragma unroll
    for (int i = 0; i < 4; i++) { int c = tid + (i<<8); out[base+c] = (v[i]-mean)*rstd*gg[c] + bb[c]; }
}

// combine the 2 expert slots + residual + LN3, write final x into d_out
__global__ void __launch_bounds__(256) moe_ln_k(const float* __restrict__ a,
                                                const float* __restrict__ gg,
                                                const float* __restrict__ bb,
                                                float* __restrict__ out)
{
    __shared__ float red[9];
    int rowid = blockIdx.x;
    size_t base = (size_t)rowid * CD;
    const float* y0 = g_yslot + (size_t)(2*rowid) * CD;
    const float* y1 = y0 + CD;
    int tid = threadIdx.x;
    float v[4];
    float s = 0.f;
#pragma unroll
    for (int i = 0; i < 4; i++) { int c = tid + (i<<8); float t = a[base+c] + y0[c] + y1[c]; v[i] = t; s += t; }
    float mean = blk_sum(s, red) * (1.f/CD);
    float qq = 0.f;
#pragma unroll
    for (int i = 0; i < 4; i++) { float d = v[i]-mean; qq += d*d; }
    float var = blk_sum(qq, red) * (1.f/CD);
    float rstd = rsqrtf(var + 1e-5f);
#pragma unroll
    for (int i = 0; i < 4; i++) { int c = tid + (i<<8); out[base+c] = (v[i]-mean)*rstd*gg[c] + bb[c]; }
}

// ---------------- router: softmax over 8 logits, top-2, renormalized gates ----------------
__global__ void __launch_bounds__(256) router_k(const float* __restrict__ x,
                                                const float* __restrict__ rw,
                                                const float* __restrict__ rb)
{
    int gw = (blockIdx.x * blockDim.x + threadIdx.x) >> 5;
    int lane = threadIdx.x & 31;
    if (gw >= CN) return;
    const float* xr = x + (size_t)gw * CD;
    float acc[8];
#pragma unroll
    for (int e = 0; e < 8; e++) acc[e] = 0.f;
    for (int d = lane; d < CD; d += 32) {
        float xv = xr[d];
        const float4* wp = (const float4*)(rw + d*CE);
        float4 w0 = wp[0], w1 = wp[1];
        acc[0] += xv*w0.x; acc[1] += xv*w0.y; acc[2] += xv*w0.z; acc[3] += xv*w0.w;
        acc[4] += xv*w1.x; acc[5] += xv*w1.y; acc[6] += xv*w1.z; acc[7] += xv*w1.w;
    }
#pragma unroll
    for (int e = 0; e < 8; e++)
#pragma unroll
        for (int o = 16; o; o >>= 1) acc[e] += __shfl_xor_sync(0xffffffffu, acc[e], o);
    if (lane == 0) {
        float p[8];
        float mx = -1e30f;
#pragma unroll
        for (int e = 0; e < 8; e++) { p[e] = acc[e] + rb[e]; mx = fmaxf(mx, p[e]); }
        float se = 0.f;
#pragma unroll
        for (int e = 0; e < 8; e++) { p[e] = __expf(p[e]-mx); se += p[e]; }
        float inv = 1.f/se;
#pragma unroll
        for (int e = 0; e < 8; e++) p[e] *= inv;
        int i1 = 0;
#pragma unroll
        for (int e = 1; e < 8; e++) if (p[e] > p[i1]) i1 = e;
        int i2 = -1;
#pragma unroll
        for (int e = 0; e < 8; e++) if (e != i1 && (i2 < 0 || p[e] > p[i2])) i2 = e;
        float s2 = p[i1] + p[i2];
        g_eid[2*gw]   = i1;  g_eid[2*gw+1]   = i2;
        g_gate[2*gw]  = p[i1]/s2; g_gate[2*gw+1] = p[i2]/s2;
    }
}

// ---------------- MoE dispatch bookkeeping ----------------
__global__ void moe_zero_k() { if (threadIdx.x < CE) g_cnt[threadIdx.x] = 0; }
__global__ void moe_count_k() {
    int i = blockIdx.x * blockDim.x + threadIdx.x;
    if (i < CNK) atomicAdd(&g_cnt[g_eid[i]], 1);
}
__global__ void moe_off_k() {
    if (threadIdx.x == 0) {
        int s = 0;
        for (int e = 0; e < CE; e++) { g_off[e] = s; g_cur[e] = s; s += g_cnt[e]; }
    }
}
__global__ void moe_build_k() {
    int i = blockIdx.x * blockDim.x + threadIdx.x;
    if (i < CNK) {
        int pos = atomicAdd(&g_cur[g_eid[i]], 1);
        g_list[pos] = i;
    }
}

// ---------------- aux loss: two-stage deterministic reduction ----------------
__global__ void __launch_bounds__(256) aux_partial_k(const float* __restrict__ x,
                                                     const float* __restrict__ rw,
                                                     const float* __restrict__ rb)
{
    __shared__ float simp[8][8];
    __shared__ float scnt[8][8];
    int tid = threadIdx.x, lane = tid & 31, w = tid >> 5;
    float imp[8], cnt[8];
#pragma unroll
    for (int e = 0; e < 8; e++) { imp[e] = 0.f; cnt[e] = 0.f; }
    for (int i = 0; i < 16; i++) {
        int t = blockIdx.x * 128 + w * 16 + i;
        const float* xr = x + (size_t)t * CD;
        float acc[8];
#pragma unroll
        for (int e = 0; e < 8; e++) acc[e] = 0.f;
        for (int d = lane; d < CD; d += 32) {
            float xv = xr[d];
            const float4* wp = (const float4*)(rw + d*CE);
            float4 w0 = wp[0], w1 = wp[1];
            acc[0] += xv*w0.x; acc[1] += xv*w0.y; acc[2] += xv*w0.z; acc[3] += xv*w0.w;
            acc[4] += xv*w1.x; acc[5] += xv*w1.y; acc[6] += xv*w1.z; acc[7] += xv*w1.w;
        }
#pragma unroll
        for (int e = 0; e < 8; e++)
#pragma unroll
            for (int o = 16; o; o >>= 1) acc[e] += __shfl_xor_sync(0xffffffffu, acc[e], o);
        if (lane == 0) {
            float p[8];
            float mx = -1e30f;
#pragma unroll
            for (int e = 0; e < 8; e++) { p[e] = acc[e] + rb[e]; mx = fmaxf(mx, p[e]); }
            float se = 0.f;
#pragma unroll
            for (int e = 0; e < 8; e++) { p[e] = __expf(p[e]-mx); se += p[e]; }
            float inv = 1.f/se;
#pragma unroll
            for (int e = 0; e < 8; e++) { p[e] *= inv; imp[e] += p[e]; }
            int i1 = 0;
#pragma unroll
            for (int e = 1; e < 8; e++) if (p[e] > p[i1]) i1 = e;
            int i2 = -1;
#pragma unroll
            for (int e = 0; e < 8; e++) if (e != i1 && (i2 < 0 || p[e] > p[i2])) i2 = e;
            cnt[i1] += 1.f; cnt[i2] += 1.f;
        }
    }
    if (lane == 0) {
#pragma unroll
        for (int e = 0; e < 8; e++) { simp[w][e] = imp[e]; scnt[w][e] = cnt[e]; }
    }
    __syncthreads();
    if (tid < 8) {
        float a = 0.f, b = 0.f;
        for (int ww = 0; ww < 8; ww++) { a += simp[ww][tid]; b += scnt[ww][tid]; }
        g_auxp[blockIdx.x][tid]     = a;
        g_auxp[blockIdx.x][8 + tid] = b;
    }
}

// Fill every output element past the x tensor with the aux scalar.
__global__ void aux_final_k(float* __restrict__ out, int out_size)
{
    if (threadIdx.x == 0 && blockIdx.x == 0) {
        float imp[8], ld[8];
        for (int e = 0; e < 8; e++) { imp[e] = 0.f; ld[e] = 0.f; }
        for (int bk = 0; bk < 32; bk++)
            for (int e = 0; e < 8; e++) { imp[e] += g_auxp[bk][e]; ld[e] += g_auxp[bk][8+e]; }
        float aux = 0.f;
        for (int e = 0; e < 8; e++) aux += (imp[e] * (1.f/CN)) * (ld[e] * (1.f/CNK));
        aux *= (float)CE;
        for (int p = CN*CD; p < out_size; p++) out[p] = aux;
    }
}

// ---------------- host launch sequence ----------------
extern "C" void kernel_launch(void* const* d_in, const int* in_sizes, int n_in,
                              void* d_out, int out_size)
{
    const float* x     = (const float*)d_in[0];
    const float* enc   = (const float*)d_in[1];
    const float* sa_wq = (const float*)d_in[2];  const float* sa_bq = (const float*)d_in[3];
    const float* sa_wk = (const float*)d_in[4];  const float* sa_bk = (const float*)d_in[5];
    const float* sa_wv = (const float*)d_in[6];  const float* sa_bv = (const float*)d_in[7];
    const float* sa_wo = (const float*)d_in[8];  const float* sa_bo = (const float*)d_in[9];
    const float* ca_wq = (const float*)d_in[10]; const float* ca_bq = (const float*)d_in[11];
    const float* ca_wk = (const float*)d_in[12]; const float* ca_bk = (const float*)d_in[13];
    const float* ca_wv = (const float*)d_in[14]; const float* ca_bv = (const float*)d_in[15];
    const float* ca_wo = (const float*)d_in[16]; const float* ca_bo = (const float*)d_in[17];
    const float* n1g   = (const float*)d_in[18]; const float* n1b   = (const float*)d_in[19];
    const float* n2g   = (const float*)d_in[20]; const float* n2b   = (const float*)d_in[21];
    const float* n3g   = (const float*)d_in[22]; const float* n3b   = (const float*)d_in[23];
    const float* rw    = (const float*)d_in[24]; const float* rb    = (const float*)d_in[25];
    const float* ew1   = (const float*)d_in[26]; const float* eb1   = (const float*)d_in[27];
    const float* ew2   = (const float*)d_in[28]; const float* eb2   = (const float*)d_in[29];
    float* out = (float*)d_out;

    float *q, *k, *v, *at, *tmp, *x1, *x2, *h, *ys;
    cudaGetSymbolAddress((void**)&q,   g_q);
    cudaGetSymbolAddress((void**)&k,   g_k);
    cudaGetSymbolAddress((void**)&v,   g_v);
    cudaGetSymbolAddress((void**)&at,  g_attn);
    cudaGetSymbolAddress((void**)&tmp, g_tmp);
    cudaGetSymbolAddress((void**)&x1,  g_x1);
    cudaGetSymbolAddress((void**)&x2,  g_x2);
    cudaGetSymbolAddress((void**)&h,   g_h);
    cudaGetSymbolAddress((void**)&ys,  g_yslot);

    cudaFuncSetAttribute(attn_tc_k, cudaFuncAttributeMaxDynamicSharedMemorySize, AT_SMEM);

    dim3 gP(CD/128, CN/128);            // single projection GEMM: (8, 32)
    dim3 gQKV(CD/128, CN/128, 3);       // fused QKV: (8, 32, 3)
    dim3 gAttn(CS/128, CH, CB);         // (16, 16, 2)

    // ---- self attention ----
    qkv_gemm_k<<<gQKV, 256>>>(x, x, sa_wq, sa_wk, sa_wv, sa_bq, sa_bk, sa_bv, q, k, v);
    attn_tc_k<<<gAttn, 256, AT_SMEM>>>(q, k, v, at);
    sgemm_k<<<gP, 256>>>(at, sa_wo, sa_bo, tmp, CN, CD, CD);
    add_ln_k<<<CN, 256>>>(x, tmp, n1g, n1b, x1);

    // ---- cross attention ----
    qkv_gemm_k<<<gQKV, 256>>>(x1, enc, ca_wq, ca_wk, ca_wv, ca_bq, ca_bk, ca_bv, q, k, v);
    attn_tc_k<<<gAttn, 256, AT_SMEM>>>(q, k, v, at);
    sgemm_k<<<gP, 256>>>(at, ca_wo, ca_bo, tmp, CN, CD, CD);
    add_ln_k<<<CN, 256>>>(x1, tmp, n2g, n2b, x2);

    // ---- MoE ----
    router_k<<<CN/8, 256>>>(x2, rw, rb);
    moe_zero_k<<<1, 32>>>();
    moe_count_k<<<CNK/256, 256>>>();
    moe_off_k<<<1, 1>>>();
    moe_build_k<<<CNK/256, 256>>>();
    moe_gemm_k<1><<<dim3(CF/128, CN/128, CE), 256>>>(x2, ew1, eb1, h,  CF, CD);
    moe_gemm_k<2><<<dim3(CD/128, CN/128, CE), 256>>>(h,  ew2, eb2, ys, CD, CF);
    moe_ln_k<<<CN, 256>>>(x2, n3g, n3b, out);

    // ---- aux loss on final x ----
    aux_partial_k<<<32, 256>>>(out, rw, rb);
    aux_final_k<<<1, 1>>>(out, out_size);
}

// round 9
// speedup vs baseline: 6.3131x; 1.0890x over previous
#include <cuda_runtime.h>
#include <math.h>
#include <stdint.h>

// Problem constants
#define CD  1024      // model dim
#define CH  16        // heads
#define CF  4096      // ffn dim
#define CE  8         // experts
#define CK  2         // top-k
#define CB  2         // batch
#define CS  2048      // seq
#define CN  (CB*CS)   // 4096 tokens
#define CDH 64        // head dim
#define CNK (CN*CK)   // 8192 assignments

// ---------------- scratch (static device globals; no allocation) ----------------
__device__ float g_q[CN*CD];
__device__ float g_k[CN*CD];
__device__ float g_v[CN*CD];
__device__ float g_attn[CN*CD];
__device__ float g_tmp[CN*CD];
__device__ float g_x1[CN*CD];
__device__ float g_x2[CN*CD];
__device__ float g_h[(size_t)CNK*CF];      // 128 MB expert hidden
__device__ float g_yslot[(size_t)CNK*CD];  // 32 MB per-slot expert outputs
__device__ float g_gate[CNK];
__device__ int   g_eid[CNK];
__device__ int   g_cnt[CE];
__device__ int   g_off[CE];
__device__ int   g_cur[CE];
__device__ int   g_list[CNK];
__device__ float g_auxp[32][16];

// ---------------- tf32 / async helpers ----------------
__device__ __forceinline__ uint32_t f2tf(float f)
{
    uint32_t r;
    asm("cvt.rna.tf32.f32 %0, %1;" : "=r"(r) : "f"(f));
    return r;
}

// mma.tf32 accepts raw fp32 bits (HW truncates mantissa to tf32)
__device__ __forceinline__ void mma_tf32(float* c, const uint32_t* a, const uint32_t* b)
{
    asm volatile("mma.sync.aligned.m16n8k8.row.col.f32.tf32.tf32.f32 "
                 "{%0,%1,%2,%3}, {%4,%5,%6,%7}, {%8,%9}, {%0,%1,%2,%3};"
                 : "+f"(c[0]), "+f"(c[1]), "+f"(c[2]), "+f"(c[3])
                 : "r"(a[0]), "r"(a[1]), "r"(a[2]), "r"(a[3]),
                   "r"(b[0]), "r"(b[1]));
}

__device__ __forceinline__ void cp16(uint32_t dst_sm, const void* src)
{
    asm volatile("cp.async.ca.shared.global [%0], [%1], 16;" :: "r"(dst_sm), "l"(src));
}
__device__ __forceinline__ void cp_commit()
{
    asm volatile("cp.async.commit_group;");
}
template<int N>
__device__ __forceinline__ void cp_wait()
{
    asm volatile("cp.async.wait_group %0;" :: "n"(N));
}

// ---------------- TF32 tensor-core GEMM body ----------------
// Block tile 128x128, k-tile 16, 256 threads = 8 warps (2x4), warp tile 64x32.
// 3-stage cp.async pipeline, raw fp32 bits in smem (HW-truncated tf32 in mma).
// Bank-conflict-free strides (A:20, B:136).
// MODE 0: dense +bias. MODE 1: fc1 gather+relu. MODE 2: fc2 scatter*(bias+acc)*gate.
template<int MODE>
__device__ __forceinline__ void tgemm_body(const float* __restrict__ A,
                                           const float* __restrict__ Bw,
                                           const float* __restrict__ bias,
                                           float* __restrict__ C,
                                           int Meff, int base, int N, int K,
                                           int bm, int bn)
{
    __shared__ uint32_t As[3][128][20];   // [m][k] raw fp32 bits
    __shared__ uint32_t Bs[3][16][136];   // [k][n] raw fp32 bits

    int tid  = threadIdx.x;
    int w    = tid >> 5, lane = tid & 31;
    int gid  = lane >> 2, tig = lane & 3;
    int wr   = (w & 1) << 6;              // warp row base: 0 / 64
    int wc   = (w >> 1) << 5;             // warp col base: 0/32/64/96

    // A global load mapping: row = tid>>1 (0..127), k-offset 0 or 8
    int ar = tid >> 1;
    int ak = (tid & 1) << 3;
    int r_ld = bm + ar;
    bool avalid = r_ld < Meff;
    const float* Arow;     // invalid rows read row 'base'/0 (finite garbage, discarded)
    if (MODE == 1) {
        int a = avalid ? g_list[base + r_ld] : g_list[base];
        Arow = A + (size_t)(a >> 1) * K;
    } else if (MODE == 2) {
        Arow = A + (size_t)(avalid ? (base + r_ld) : base) * K;
    } else {
        Arow = A + (size_t)(avalid ? r_ld : 0) * K;
    }
    // B global load mapping: k-row = tid>>4 (0..15), col chunk of 8
    int br = tid >> 4;
    int bc = (tid & 15) << 3;
    const float* Bp = Bw + (size_t)br * N + bn + bc;

    uint32_t a_dst[3], b_dst[3];
#pragma unroll
    for (int s = 0; s < 3; s++) {
        a_dst[s] = (uint32_t)__cvta_generic_to_shared(&As[s][ar][ak]);
        b_dst[s] = (uint32_t)__cvta_generic_to_shared(&Bs[s][br][bc]);
    }

    float acc[4][4][4];
#pragma unroll
    for (int i = 0; i < 4; i++)
#pragma unroll
        for (int j = 0; j < 4; j++)
#pragma unroll
            for (int q = 0; q < 4; q++) acc[i][j][q] = 0.f;

    int nT = K >> 4;

    // prologue: stages 0 and 1 in flight
#pragma unroll
    for (int s = 0; s < 2; s++) {
        const float* Ap = Arow + s*16 + ak;
        const float* Bq = Bp + (size_t)s * 16 * N;
        cp16(a_dst[s],      Ap);
        cp16(a_dst[s] + 16, Ap + 4);
        cp16(b_dst[s],      Bq);
        cp16(b_dst[s] + 16, Bq + 4);
        cp_commit();
    }

    int cur = 0;
    for (int t = 0; t < nT; t++) {
        cp_wait<1>();        // stage t landed (t+1 may still be in flight)
        __syncthreads();     // all threads' stage-t data visible; prev reads done

        // issue stage t+2 into buffer freed at t-1
        if (t + 2 < nT) {
            int nx = cur + 2; if (nx >= 3) nx -= 3;
            const float* Ap = Arow + (t+2)*16 + ak;
            const float* Bq = Bp + (size_t)(t+2) * 16 * N;
            cp16(a_dst[nx],      Ap);
            cp16(a_dst[nx] + 16, Ap + 4);
            cp16(b_dst[nx],      Bq);
            cp16(b_dst[nx] + 16, Bq + 4);
            cp_commit();
        }

#pragma unroll
        for (int ks = 0; ks < 2; ks++) {
            int koff = ks << 3;
            uint32_t af[4][4], bf[4][2];
#pragma unroll
            for (int i = 0; i < 4; i++) {
                int r = wr + i*16 + gid;
                af[i][0] = As[cur][r][koff+tig];
                af[i][1] = As[cur][r+8][koff+tig];
                af[i][2] = As[cur][r][koff+tig+4];
                af[i][3] = As[cur][r+8][koff+tig+4];
            }
#pragma unroll
            for (int j = 0; j < 4; j++) {
                int n = wc + j*8 + gid;
                bf[j][0] = Bs[cur][koff+tig][n];
                bf[j][1] = Bs[cur][koff+tig+4][n];
            }
#pragma unroll
            for (int i = 0; i < 4; i++)
#pragma unroll
                for (int j = 0; j < 4; j++)
                    mma_tf32(acc[i][j], af[i], bf[j]);
        }
        if (++cur == 3) cur = 0;
    }

    // epilogue: c0,c1 at row gid; c2,c3 at row gid+8; cols tig*2, tig*2+1
#pragma unroll
    for (int i = 0; i < 4; i++) {
#pragma unroll
        for (int half = 0; half < 2; half++) {
            int r = bm + wr + i*16 + gid + half*8;
            if (r >= Meff) continue;
            float* Crow;
            float scale = 1.f;
            if (MODE == 2) {
                int a  = g_list[base + r];
                scale  = g_gate[a];
                Crow   = C + (size_t)a * N;
            } else if (MODE == 1) {
                Crow   = C + (size_t)(base + r) * N;
            } else {
                Crow   = C + (size_t)r * N;
            }
#pragma unroll
            for (int j = 0; j < 4; j++) {
                int col = bn + wc + j*8 + tig*2;
                float v0 = acc[i][j][half*2+0] + bias[col];
                float v1 = acc[i][j][half*2+1] + bias[col+1];
                if (MODE == 1) { v0 = fmaxf(v0, 0.f); v1 = fmaxf(v1, 0.f); }
                if (MODE == 2) { v0 *= scale; v1 *= scale; }
                *(float2*)(Crow + col) = make_float2(v0, v1);
            }
        }
    }
}

// dense single GEMM
__global__ void __launch_bounds__(256, 2) sgemm_k(const float* __restrict__ A,
                                                  const float* __restrict__ Bw,
                                                  const float* __restrict__ bias,
                                                  float* __restrict__ C,
                                                  int M, int N, int K)
{
    tgemm_body<0>(A, Bw, bias, C, M, 0, N, K, blockIdx.y * 128, blockIdx.x * 128);
}

// fused QKV projection: blockIdx.z selects (A, W, bias, C) triple.
__global__ void __launch_bounds__(256, 2) qkv_gemm_k(const float* __restrict__ Aq,
                                                     const float* __restrict__ Akv,
                                                     const float* __restrict__ Wq,
                                                     const float* __restrict__ Wk,
                                                     const float* __restrict__ Wv,
                                                     const float* __restrict__ bq,
                                                     const float* __restrict__ bk,
                                                     const float* __restrict__ bv,
                                                     float* __restrict__ Cq,
                                                     float* __restrict__ Ck,
                                                     float* __restrict__ Cv)
{
    int z = blockIdx.z;
    const float* A  = (z == 0) ? Aq : Akv;
    const float* W  = (z == 0) ? Wq : (z == 1) ? Wk : Wv;
    const float* bb = (z == 0) ? bq : (z == 1) ? bk : bv;
    float*       C  = (z == 0) ? Cq : (z == 1) ? Ck : Cv;
    tgemm_body<0>(A, W, bb, C, CN, 0, CD, CD, blockIdx.y * 128, blockIdx.x * 128);
}

// grouped expert GEMMs (MODE 1 = fc1+relu gather, MODE 2 = fc2 scatter*gate)
template<int MODE>
__global__ void __launch_bounds__(256, 2) moe_gemm_k(const float* __restrict__ A,
                                                     const float* __restrict__ Bw,
                                                     const float* __restrict__ bias,
                                                     float* __restrict__ C,
                                                     int N, int K)
{
    int e = blockIdx.z;
    int Meff = g_cnt[e];
    int base = g_off[e];
    int bm = blockIdx.y * 128;
    if (bm >= Meff) return;
    tgemm_body<MODE>(A, Bw + (size_t)e * K * N, bias + (size_t)e * N, C,
                     Meff, base, N, K, bm, blockIdx.x * 128);
}

// ---------------- TF32 tensor-core flash attention ----------------
// Block: 128 q-rows, 8 warps x 16 rows each; kv tiles of 64.
// smem rows stride 72 words -> conflict-free fragment access patterns.
// Q pre-scaled by 1/sqrt(DH) at fragment load. P re-layout via per-warp smem.
#define AT_SMEM ((64*72 + 64*72 + 128*72)*4)

__global__ void __launch_bounds__(256, 2) attn_tc_k(const float* __restrict__ Q,
                                                    const float* __restrict__ Kg,
                                                    const float* __restrict__ Vg,
                                                    float* __restrict__ O)
{
    extern __shared__ uint32_t smw[];
    uint32_t* ks = smw;               // [64][72]
    uint32_t* vs = smw + 64*72;       // [64][72]
    uint32_t* ps = smw + 2*64*72;     // [128][72]

    int tid  = threadIdx.x;
    int w    = tid >> 5, lane = tid & 31;
    int gid  = lane >> 2, tig = lane & 3;
    int h = blockIdx.y, b = blockIdx.z;
    int q0 = blockIdx.x * 128;
    size_t basebh = ((size_t)b*CS)*CD + (size_t)h*CDH;
    int wbase = w << 4;               // warp's q-row base within block

    // Q fragments for this warp's 16 rows (scaled by 0.125 = 1/sqrt(64))
    uint32_t qa[8][4];
    {
        const float* Qb = Q + basebh + (size_t)(q0 + wbase) * CD;
#pragma unroll
        for (int kk = 0; kk < 8; kk++) {
            int c = kk*8 + tig;
            qa[kk][0] = f2tf(0.125f * Qb[(size_t)gid*CD + c]);
            qa[kk][1] = f2tf(0.125f * Qb[(size_t)(gid+8)*CD + c]);
            qa[kk][2] = f2tf(0.125f * Qb[(size_t)gid*CD + c + 4]);
            qa[kk][3] = f2tf(0.125f * Qb[(size_t)(gid+8)*CD + c + 4]);
        }
    }

    float m0 = -1e30f, m1 = -1e30f, l0 = 0.f, l1 = 0.f;
    float oacc[8][4];
#pragma unroll
    for (int j = 0; j < 8; j++)
#pragma unroll
        for (int q = 0; q < 4; q++) oacc[j][q] = 0.f;

    int lr = tid >> 4;              // 0..15
    int lc = (tid & 15) << 2;       // 0..60

    for (int kv0 = 0; kv0 < CS; kv0 += 64) {
        __syncthreads();   // all warps done reading ks/vs of previous tile
        {
            const float* Kb = Kg + basebh + (size_t)kv0 * CD;
            const float* Vb = Vg + basebh + (size_t)kv0 * CD;
#pragma unroll
            for (int rr = lr; rr < 64; rr += 16) {
                float4 k4 = *(const float4*)(Kb + (size_t)rr*CD + lc);
                float4 v4 = *(const float4*)(Vb + (size_t)rr*CD + lc);
                *(uint4*)&ks[rr*72 + lc] = make_uint4(f2tf(k4.x), f2tf(k4.y), f2tf(k4.z), f2tf(k4.w));
                *(uint4*)&vs[rr*72 + lc] = make_uint4(f2tf(v4.x), f2tf(v4.y), f2tf(v4.z), f2tf(v4.w));
            }
        }
        __syncthreads();

        // S = Q K^T  (16 x 64 per warp)
        float sacc[8][4];
#pragma unroll
        for (int j = 0; j < 8; j++)
#pragma unroll
            for (int q = 0; q < 4; q++) sacc[j][q] = 0.f;
#pragma unroll
        for (int kk = 0; kk < 8; kk++) {
            int koff = kk << 3;
#pragma unroll
            for (int j = 0; j < 8; j++) {
                uint32_t bq[2];
                int n = j*8 + gid;
                bq[0] = ks[n*72 + koff + tig];
                bq[1] = ks[n*72 + koff + tig + 4];
                mma_tf32(sacc[j], qa[kk], bq);
            }
        }

        // online softmax (two rows per lane: r0=gid, r1=gid+8)
        float mx0 = -1e30f, mx1 = -1e30f;
#pragma unroll
        for (int j = 0; j < 8; j++) {
            mx0 = fmaxf(mx0, fmaxf(sacc[j][0], sacc[j][1]));
            mx1 = fmaxf(mx1, fmaxf(sacc[j][2], sacc[j][3]));
        }
        mx0 = fmaxf(mx0, __shfl_xor_sync(0xffffffffu, mx0, 1));
        mx0 = fmaxf(mx0, __shfl_xor_sync(0xffffffffu, mx0, 2));
        mx1 = fmaxf(mx1, __shfl_xor_sync(0xffffffffu, mx1, 1));
        mx1 = fmaxf(mx1, __shfl_xor_sync(0xffffffffu, mx1, 2));
        float nm0 = fmaxf(m0, mx0), nm1 = fmaxf(m1, mx1);
        float cr0 = __expf(m0 - nm0), cr1 = __expf(m1 - nm1);
        float ls0 = 0.f, ls1 = 0.f;
        int pr0 = (wbase + gid) * 72;
        int pr1 = (wbase + gid + 8) * 72;
#pragma unroll
        for (int j = 0; j < 8; j++) {
            float p0 = __expf(sacc[j][0] - nm0);
            float p1 = __expf(sacc[j][1] - nm0);
            float p2 = __expf(sacc[j][2] - nm1);
            float p3 = __expf(sacc[j][3] - nm1);
            ls0 += p0 + p1;
            ls1 += p2 + p3;
            int c = j*8 + 2*tig;
            *(uint2*)&ps[pr0 + c] = make_uint2(f2tf(p0), f2tf(p1));
            *(uint2*)&ps[pr1 + c] = make_uint2(f2tf(p2), f2tf(p3));
        }
        ls0 += __shfl_xor_sync(0xffffffffu, ls0, 1);
        ls0 += __shfl_xor_sync(0xffffffffu, ls0, 2);
        ls1 += __shfl_xor_sync(0xffffffffu, ls1, 1);
        ls1 += __shfl_xor_sync(0xffffffffu, ls1, 2);
        l0 = l0*cr0 + ls0;  m0 = nm0;
        l1 = l1*cr1 + ls1;  m1 = nm1;
#pragma unroll
        for (int j = 0; j < 8; j++) {
            oacc[j][0] *= cr0; oacc[j][1] *= cr0;
            oacc[j][2] *= cr1; oacc[j][3] *= cr1;
        }
        __syncwarp();   // ps rows of this warp visible to all its lanes

        // O += P V  (16 x 64 per warp)
#pragma unroll
        for (int kk = 0; kk < 8; kk++) {
            int koff = kk << 3;
            uint32_t pa[4];
            pa[0] = ps[pr0 + koff + tig];
            pa[1] = ps[pr1 + koff + tig];
            pa[2] = ps[pr0 + koff + tig + 4];
            pa[3] = ps[pr1 + koff + tig + 4];
#pragma unroll
            for (int j = 0; j < 8; j++) {
                uint32_t vb[2];
                int n = j*8 + gid;
                vb[0] = vs[(koff + tig)*72 + n];
                vb[1] = vs[(koff + tig + 4)*72 + n];
                mma_tf32(oacc[j], pa, vb);
            }
        }
        __syncwarp();   // all lanes done reading ps before next overwrite
    }

    float inv0 = 1.f / l0, inv1 = 1.f / l1;
    float* Ob = O + basebh + (size_t)(q0 + wbase) * CD;
#pragma unroll
    for (int j = 0; j < 8; j++) {
        int c = j*8 + 2*tig;
        *(float2*)(Ob + (size_t)gid*CD + c)     = make_float2(oacc[j][0]*inv0, oacc[j][1]*inv0);
        *(float2*)(Ob + (size_t)(gid+8)*CD + c) = make_float2(oacc[j][2]*inv1, oacc[j][3]*inv1);
    }
}

// ---------------- block reduce helper ----------------
__device__ __forceinline__ float blk_sum(float v, float* red)
{
    int lane = threadIdx.x & 31, w = threadIdx.x >> 5;
#pragma unroll
    for (int o = 16; o; o >>= 1) v += __shfl_xor_sync(0xffffffffu, v, o);
    if (lane == 0) red[w] = v;
    __syncthreads();
    if (threadIdx.x == 0) {
        float t = 0.f;
        for (int i = 0; i < 8; i++) t += red[i];
        red[8] = t;
    }
    __syncthreads();
    float r = red[8];
    __syncthreads();
    return r;
}

// ---------------- residual add + layernorm (row = 1024) ----------------
__global__ void __launch_bounds__(256) add_ln_k(const float* __restrict__ a,
                                                const float* __restrict__ b,
                                                const float* __restrict__ gg,
                                                const float* __restrict__ bb,
                                                float* __restrict__ out)
{
    __shared__ float red[9];
    size_t base = (size_t)blockIdx.x * CD;
    int tid = threadIdx.x;
    float v[4];
    float s = 0.f;
#pragma unroll
    for (int i = 0; i < 4; i++) { int c = tid + (i<<8); float t = a[base+c] + b[base+c]; v[i] = t; s += t; }
    float mean = blk_sum(s, red) * (1.f/CD);
    float qq = 0.f;
#pragma unroll
    for (int i = 0; i < 4; i++) { float d = v[i]-mean; qq += d*d; }
    float var = blk_sum(qq, red) * (1.f/CD);
    float rstd = rsqrtf(var + 1e-5f);
#pragma unroll
    for (int i = 0; i < 4; i++) { int c = tid + (i<<8); out[base+c] = (v[i]-mean)*rstd*gg[c] + bb[c]; }
}

// combine the 2 expert slots + residual + LN3, write final x into d_out
__global__ void __launch_bounds__(256) moe_ln_k(const float* __restrict__ a,
                                                const float* __restrict__ gg,
                                                const float* __restrict__ bb,
                                                float* __restrict__ out)
{
    __shared__ float red[9];
    int rowid = blockIdx.x;
    size_t base = (size_t)rowid * CD;
    const float* y0 = g_yslot + (size_t)(2*rowid) * CD;
    const float* y1 = y0 + CD;
    int tid = threadIdx.x;
    float v[4];
    float s = 0.f;
#pragma unroll
    for (int i = 0; i < 4; i++) { int c = tid + (i<<8); float t = a[base+c] + y0[c] + y1[c]; v[i] = t; s += t; }
    float mean = blk_sum(s, red) * (1.f/CD);
    float qq = 0.f;
#pragma unroll
    for (int i = 0; i < 4; i++) { float d = v[i]-mean; qq += d*d; }
    float var = blk_sum(qq, red) * (1.f/CD);
    float rstd = rsqrtf(var + 1e-5f);
#pragma unroll
    for (int i = 0; i < 4; i++) { int c = tid + (i<<8); out[base+c] = (v[i]-mean)*rstd*gg[c] + bb[c]; }
}

// ---------------- router: softmax over 8 logits, top-2, renormalized gates ----------------
__global__ void __launch_bounds__(256) router_k(const float* __restrict__ x,
                                                const float* __restrict__ rw,
                                                const float* __restrict__ rb)
{
    int gw = (blockIdx.x * blockDim.x + threadIdx.x) >> 5;
    int lane = threadIdx.x & 31;
    if (gw >= CN) return;
    const float* xr = x + (size_t)gw * CD;
    float acc[8];
#pragma unroll
    for (int e = 0; e < 8; e++) acc[e] = 0.f;
    for (int d = lane; d < CD; d += 32) {
        float xv = xr[d];
        const float4* wp = (const float4*)(rw + d*CE);
        float4 w0 = wp[0], w1 = wp[1];
        acc[0] += xv*w0.x; acc[1] += xv*w0.y; acc[2] += xv*w0.z; acc[3] += xv*w0.w;
        acc[4] += xv*w1.x; acc[5] += xv*w1.y; acc[6] += xv*w1.z; acc[7] += xv*w1.w;
    }
#pragma unroll
    for (int e = 0; e < 8; e++)
#pragma unroll
        for (int o = 16; o; o >>= 1) acc[e] += __shfl_xor_sync(0xffffffffu, acc[e], o);
    if (lane == 0) {
        float p[8];
        float mx = -1e30f;
#pragma unroll
        for (int e = 0; e < 8; e++) { p[e] = acc[e] + rb[e]; mx = fmaxf(mx, p[e]); }
        float se = 0.f;
#pragma unroll
        for (int e = 0; e < 8; e++) { p[e] = __expf(p[e]-mx); se += p[e]; }
        float inv = 1.f/se;
#pragma unroll
        for (int e = 0; e < 8; e++) p[e] *= inv;
        int i1 = 0;
#pragma unroll
        for (int e = 1; e < 8; e++) if (p[e] > p[i1]) i1 = e;
        int i2 = -1;
#pragma unroll
        for (int e = 0; e < 8; e++) if (e != i1 && (i2 < 0 || p[e] > p[i2])) i2 = e;
        float s2 = p[i1] + p[i2];
        g_eid[2*gw]   = i1;  g_eid[2*gw+1]   = i2;
        g_gate[2*gw]  = p[i1]/s2; g_gate[2*gw+1] = p[i2]/s2;
    }
}

// ---------------- MoE dispatch bookkeeping ----------------
__global__ void moe_zero_k() { if (threadIdx.x < CE) g_cnt[threadIdx.x] = 0; }
__global__ void moe_count_k() {
    int i = blockIdx.x * blockDim.x + threadIdx.x;
    if (i < CNK) atomicAdd(&g_cnt[g_eid[i]], 1);
}
__global__ void moe_off_k() {
    if (threadIdx.x == 0) {
        int s = 0;
        for (int e = 0; e < CE; e++) { g_off[e] = s; g_cur[e] = s; s += g_cnt[e]; }
    }
}
__global__ void moe_build_k() {
    int i = blockIdx.x * blockDim.x + threadIdx.x;
    if (i < CNK) {
        int pos = atomicAdd(&g_cur[g_eid[i]], 1);
        g_list[pos] = i;
    }
}

// ---------------- aux loss: two-stage deterministic reduction ----------------
__global__ void __launch_bounds__(256) aux_partial_k(const float* __restrict__ x,
                                                     const float* __restrict__ rw,
                                                     const float* __restrict__ rb)
{
    __shared__ float simp[8][8];
    __shared__ float scnt[8][8];
    int tid = threadIdx.x, lane = tid & 31, w = tid >> 5;
    float imp[8], cnt[8];
#pragma unroll
    for (int e = 0; e < 8; e++) { imp[e] = 0.f; cnt[e] = 0.f; }
    for (int i = 0; i < 16; i++) {
        int t = blockIdx.x * 128 + w * 16 + i;
        const float* xr = x + (size_t)t * CD;
        float acc[8];
#pragma unroll
        for (int e = 0; e < 8; e++) acc[e] = 0.f;
        for (int d = lane; d < CD; d += 32) {
            float xv = xr[d];
            const float4* wp = (const float4*)(rw + d*CE);
            float4 w0 = wp[0], w1 = wp[1];
            acc[0] += xv*w0.x; acc[1] += xv*w0.y; acc[2] += xv*w0.z; acc[3] += xv*w0.w;
            acc[4] += xv*w1.x; acc[5] += xv*w1.y; acc[6] += xv*w1.z; acc[7] += xv*w1.w;
        }
#pragma unroll
        for (int e = 0; e < 8; e++)
#pragma unroll
            for (int o = 16; o; o >>= 1) acc[e] += __shfl_xor_sync(0xffffffffu, acc[e], o);
        if (lane == 0) {
            float p[8];
            float mx = -1e30f;
#pragma unroll
            for (int e = 0; e < 8; e++) { p[e] = acc[e] + rb[e]; mx = fmaxf(mx, p[e]); }
            float se = 0.f;
#pragma unroll
            for (int e = 0; e < 8; e++) { p[e] = __expf(p[e]-mx); se += p[e]; }
            float inv = 1.f/se;
#pragma unroll
            for (int e = 0; e < 8; e++) { p[e] *= inv; imp[e] += p[e]; }
            int i1 = 0;
#pragma unroll
            for (int e = 1; e < 8; e++) if (p[e] > p[i1]) i1 = e;
            int i2 = -1;
#pragma unroll
            for (int e = 0; e < 8; e++) if (e != i1 && (i2 < 0 || p[e] > p[i2])) i2 = e;
            cnt[i1] += 1.f; cnt[i2] += 1.f;
        }
    }
    if (lane == 0) {
#pragma unroll
        for (int e = 0; e < 8; e++) { simp[w][e] = imp[e]; scnt[w][e] = cnt[e]; }
    }
    __syncthreads();
    if (tid < 8) {
        float a = 0.f, b = 0.f;
        for (int ww = 0; ww < 8; ww++) { a += simp[ww][tid]; b += scnt[ww][tid]; }
        g_auxp[blockIdx.x][tid]     = a;
        g_auxp[blockIdx.x][8 + tid] = b;
    }
}

// Fill every output element past the x tensor with the aux scalar.
__global__ void aux_final_k(float* __restrict__ out, int out_size)
{
    if (threadIdx.x == 0 && blockIdx.x == 0) {
        float imp[8], ld[8];
        for (int e = 0; e < 8; e++) { imp[e] = 0.f; ld[e] = 0.f; }
        for (int bk = 0; bk < 32; bk++)
            for (int e = 0; e < 8; e++) { imp[e] += g_auxp[bk][e]; ld[e] += g_auxp[bk][8+e]; }
        float aux = 0.f;
        for (int e = 0; e < 8; e++) aux += (imp[e] * (1.f/CN)) * (ld[e] * (1.f/CNK));
        aux *= (float)CE;
        for (int p = CN*CD; p < out_size; p++) out[p] = aux;
    }
}

// ---------------- host launch sequence ----------------
extern "C" void kernel_launch(void* const* d_in, const int* in_sizes, int n_in,
                              void* d_out, int out_size)
{
    const float* x     = (const float*)d_in[0];
    const float* enc   = (const float*)d_in[1];
    const float* sa_wq = (const float*)d_in[2];  const float* sa_bq = (const float*)d_in[3];
    const float* sa_wk = (const float*)d_in[4];  const float* sa_bk = (const float*)d_in[5];
    const float* sa_wv = (const float*)d_in[6];  const float* sa_bv = (const float*)d_in[7];
    const float* sa_wo = (const float*)d_in[8];  const float* sa_bo = (const float*)d_in[9];
    const float* ca_wq = (const float*)d_in[10]; const float* ca_bq = (const float*)d_in[11];
    const float* ca_wk = (const float*)d_in[12]; const float* ca_bk = (const float*)d_in[13];
    const float* ca_wv = (const float*)d_in[14]; const float* ca_bv = (const float*)d_in[15];
    const float* ca_wo = (const float*)d_in[16]; const float* ca_bo = (const float*)d_in[17];
    const float* n1g   = (const float*)d_in[18]; const float* n1b   = (const float*)d_in[19];
    const float* n2g   = (const float*)d_in[20]; const float* n2b   = (const float*)d_in[21];
    const float* n3g   = (const float*)d_in[22]; const float* n3b   = (const float*)d_in[23];
    const float* rw    = (const float*)d_in[24]; const float* rb    = (const float*)d_in[25];
    const float* ew1   = (const float*)d_in[26]; const float* eb1   = (const float*)d_in[27];
    const float* ew2   = (const float*)d_in[28]; const float* eb2   = (const float*)d_in[29];
    float* out = (float*)d_out;

    float *q, *k, *v, *at, *tmp, *x1, *x2, *h, *ys;
    cudaGetSymbolAddress((void**)&q,   g_q);
    cudaGetSymbolAddress((void**)&k,   g_k);
    cudaGetSymbolAddress((void**)&v,   g_v);
    cudaGetSymbolAddress((void**)&at,  g_attn);
    cudaGetSymbolAddress((void**)&tmp, g_tmp);
    cudaGetSymbolAddress((void**)&x1,  g_x1);
    cudaGetSymbolAddress((void**)&x2,  g_x2);
    cudaGetSymbolAddress((void**)&h,   g_h);
    cudaGetSymbolAddress((void**)&ys,  g_yslot);

    cudaFuncSetAttribute(attn_tc_k, cudaFuncAttributeMaxDynamicSharedMemorySize, AT_SMEM);

    dim3 gP(CD/128, CN/128);            // single projection GEMM: (8, 32)
    dim3 gQKV(CD/128, CN/128, 3);       // fused QKV: (8, 32, 3)
    dim3 gAttn(CS/128, CH, CB);         // (16, 16, 2)

    // ---- self attention ----
    qkv_gemm_k<<<gQKV, 256>>>(x, x, sa_wq, sa_wk, sa_wv, sa_bq, sa_bk, sa_bv, q, k, v);
    attn_tc_k<<<gAttn, 256, AT_SMEM>>>(q, k, v, at);
    sgemm_k<<<gP, 256>>>(at, sa_wo, sa_bo, tmp, CN, CD, CD);
    add_ln_k<<<CN, 256>>>(x, tmp, n1g, n1b, x1);

    // ---- cross attention ----
    qkv_gemm_k<<<gQKV, 256>>>(x1, enc, ca_wq, ca_wk, ca_wv, ca_bq, ca_bk, ca_bv, q, k, v);
    attn_tc_k<<<gAttn, 256, AT_SMEM>>>(q, k, v, at);
    sgemm_k<<<gP, 256>>>(at, ca_wo, ca_bo, tmp, CN, CD, CD);
    add_ln_k<<<CN, 256>>>(x1, tmp, n2g, n2b, x2);

    // ---- MoE ----
    router_k<<<CN/8, 256>>>(x2, rw, rb);
    moe_zero_k<<<1, 32>>>();
    moe_count_k<<<CNK/256, 256>>>();
    moe_off_k<<<1, 1>>>();
    moe_build_k<<<CNK/256, 256>>>();
    moe_gemm_k<1><<<dim3(CF/128, CN/128, CE), 256>>>(x2, ew1, eb1, h,  CF, CD);
    moe_gemm_k<2><<<dim3(CD/128, CN/128, CE), 256>>>(h,  ew2, eb2, ys, CD, CF);
    moe_ln_k<<<CN, 256>>>(x2, n3g, n3b, out);

    // ---- aux loss on final x ----
    aux_partial_k<<<32, 256>>>(out, rw, rb);
    aux_final_k<<<1, 1>>>(out, out_size);
}